// round 12
// baseline (speedup 1.0000x reference)
#include <cuda_runtime.h>
#include <cuda_bf16.h>
#include <cstdint>

typedef __nv_bfloat16 bf16;

// ---------------- problem constants ----------------
#define NN   16384
#define FF   128
#define RR   16
#define HH   8
#define CC   64
#define HC   512
#define NE   163840
#define NEP  180224          // NE + NN self loops
#define NEG_SLOPE 0.2f
#define SELF_FILL 0.5f

// ---------------- device scratch (only ever touched from device code) ----------------
__device__ int   g_is64;
__device__ int   g_bad;
__device__ int   g_src32[NE];
__device__ int   g_dst32[NE];
__device__ int   g_deg[NN];
__device__ int   g_off[NN + 1];
__device__ int   g_fill[NN];
__device__ int2  g_csr[NEP];          // packed {src, eid}
__device__ float g_xl1[(size_t)NN * HC];
__device__ float g_xr1[(size_t)NN * HC];
__device__ float g_h1 [(size_t)NN * HC];
__device__ float g_xl2[(size_t)NN * HC];
__device__ float g_xr2[(size_t)NN * HC];
__device__ __align__(16) bf16 g_xs_hi[(size_t)NN * FF];
__device__ __align__(16) bf16 g_xs_lo[(size_t)NN * FF];
__device__ __align__(16) bf16 g_hs_hi[(size_t)NN * HC];
__device__ __align__(16) bf16 g_hs_lo[(size_t)NN * HC];
__device__ __align__(16) bf16 g_wl_hi[HC * HC];
__device__ __align__(16) bf16 g_wl_lo[HC * HC];
__device__ __align__(16) bf16 g_wr_hi[HC * HC];
__device__ __align__(16) bf16 g_wr_lo[HC * HC];

// ---------------- asm helpers ----------------
#define LDSM_X4(r0, r1, r2, r3, a) \
    asm volatile("ldmatrix.sync.aligned.m8n8.x4.shared.b16 {%0,%1,%2,%3}, [%4];" \
                 : "=r"(r0), "=r"(r1), "=r"(r2), "=r"(r3) : "r"(a))

#define MMA_BF16(d, a0, a1, a2, a3, b0, b1) \
    asm volatile("mma.sync.aligned.m16n8k16.row.col.f32.bf16.bf16.f32 " \
                 "{%0,%1,%2,%3}, {%4,%5,%6,%7}, {%8,%9}, {%0,%1,%2,%3};" \
                 : "+f"((d)[0]), "+f"((d)[1]), "+f"((d)[2]), "+f"((d)[3]) \
                 : "r"(a0), "r"(a1), "r"(a2), "r"(a3), "r"(b0), "r"(b1))

#define CP_ASYNC16(dst, src) \
    asm volatile("cp.async.cg.shared.global [%0], [%1], 16;" :: "r"(dst), "l"(src))
#define CP_COMMIT()  asm volatile("cp.async.commit_group;" ::: "memory")
#define CP_WAIT0()   asm volatile("cp.async.wait_group 0;" ::: "memory")
#define CP_WAIT1()   asm volatile("cp.async.wait_group 1;" ::: "memory")

__device__ __forceinline__ uint32_t smem_to_u32(const void* p) {
    uint32_t a;
    asm("{ .reg .u64 t; cvta.to.shared.u64 t, %1; cvt.u32.u64 %0, t; }" : "=r"(a) : "l"(p));
    return a;
}
__device__ __forceinline__ void fma2(unsigned long long& d, unsigned long long a,
                                     unsigned long long b) {
    asm("fma.rn.f32x2 %0, %1, %2, %0;" : "+l"(d) : "l"(a), "l"(b));
}
__device__ __forceinline__ unsigned long long pack2(float a, float b) {
    unsigned long long r;
    asm("mov.b64 %0, {%1, %2};" : "=l"(r) : "f"(a), "f"(b));
    return r;
}
__device__ __forceinline__ float2 unpack2(unsigned long long v) {
    float2 f;
    asm("mov.b64 {%0, %1}, %2;" : "=f"(f.x), "=f"(f.y) : "l"(v));
    return f;
}
__device__ __forceinline__ uint32_t pkbf(bf16 a, bf16 b) {
    uint16_t ua = *(uint16_t*)&a, ub = *(uint16_t*)&b;
    return (uint32_t)ua | ((uint32_t)ub << 16);
}

// ---------------- dtype detect / convert / CSR ----------------
__global__ void k_detect(const long long* ei) {
    __shared__ int ok;
    if (threadIdx.x == 0) ok = 1;
    __syncthreads();
    for (int i = threadIdx.x; i < 2048; i += blockDim.x) {
        long long v = ei[i];
        if (v < 0 || v >= NN) ok = 0;
    }
    __syncthreads();
    if (threadIdx.x == 0) g_is64 = ok;
}
__global__ void k_init_deg() {
    int n = blockIdx.x * blockDim.x + threadIdx.x;
    if (n < NN) g_deg[n] = 1;
    if (n == 0) g_bad = 0;
}
__global__ void k_convert(const void* ei) {
    int e = blockIdx.x * blockDim.x + threadIdx.x;
    if (e >= NE) return;
    int s, d;
    if (g_is64) {
        const long long* p = (const long long*)ei;
        s = (int)p[e]; d = (int)p[NE + e];
    } else {
        const int* p = (const int*)ei;
        s = p[e]; d = p[NE + e];
    }
    g_src32[e] = s; g_dst32[e] = d;
    atomicAdd(&g_deg[d], 1);
}
__global__ void k_scan() {
    const int PER = NN / 1024;
    int t = threadIdx.x, lane = t & 31, warp = t >> 5;
    int base = t * PER;
    int loc[PER]; int run = 0;
#pragma unroll
    for (int i = 0; i < PER; i++) { loc[i] = run; run += g_deg[base + i]; }
    int v = run;
#pragma unroll
    for (int o = 1; o < 32; o <<= 1) { int u = __shfl_up_sync(~0u, v, o); if (lane >= o) v += u; }
    __shared__ int ws[32];
    if (lane == 31) ws[warp] = v;
    __syncthreads();
    if (warp == 0) {
        int w = ws[lane];
#pragma unroll
        for (int o = 1; o < 32; o <<= 1) { int u = __shfl_up_sync(~0u, w, o); if (lane >= o) w += u; }
        ws[lane] = w;
    }
    __syncthreads();
    int excl = (warp ? ws[warp - 1] : 0) + (v - run);
#pragma unroll
    for (int i = 0; i < PER; i++) { int o = excl + loc[i]; g_off[base + i] = o; g_fill[base + i] = o; }
    if (t == 1023) g_off[NN] = excl + run;
}
__global__ void k_scatter() {
    int e = blockIdx.x * blockDim.x + threadIdx.x;
    if (e >= NEP) return;
    int s = (e < NE) ? g_src32[e] : (e - NE);
    int d = (e < NE) ? g_dst32[e] : (e - NE);
    int pos = atomicAdd(&g_fill[d], 1);
    g_csr[pos] = make_int2(s, e);
}

// ---------------- split / transpose (globals bound in device code) ----------------
__device__ __forceinline__ void split1(float v, bf16& h, bf16& l) {
    h = __float2bfloat16(v);
    l = __float2bfloat16(v - __bfloat162float(h));
}
__global__ void k_split_x(const float* __restrict__ src) {
    int i = blockIdx.x * blockDim.x + threadIdx.x;
    if (i >= NN * FF) return;
    split1(src[i], g_xs_hi[i], g_xs_lo[i]);
}
// coalesced W[K,512] -> Wt[512,K] transpose+split, BOTH weight matrices in one kernel
__global__ void k_wT_both(const float* __restrict__ Wl, const float* __restrict__ Wr,
                          int K) {
    __shared__ float tl[32][33];
    __shared__ float tr[32][33];
    int tx = threadIdx.x, ty = threadIdx.y;
    int kt = blockIdx.x * 32, nt = blockIdx.y * 32;
#pragma unroll
    for (int r = ty; r < 32; r += 8) {
        tl[r][tx] = Wl[(size_t)(kt + r) * HC + nt + tx];
        tr[r][tx] = Wr[(size_t)(kt + r) * HC + nt + tx];
    }
    __syncthreads();
#pragma unroll
    for (int r = ty; r < 32; r += 8) {
        size_t o = (size_t)(nt + r) * K + kt + tx;
        bf16 h, l;
        split1(tl[tx][r], h, l); g_wl_hi[o] = h; g_wl_lo[o] = l;
        split1(tr[tx][r], h, l); g_wr_hi[o] = h; g_wr_lo[o] = l;
    }
}

// ---------------- bf16 HMMA GEMM (proven: 128x128, 256 thr, 2-stage) ----------------
#define KC       16
#define SPITCH   48
#define TILE_SB  (128 * SPITCH)     // 6144
#define STAGE_B  (4 * TILE_SB)      // 24576; 2 stages = 49152 static smem

__device__ __forceinline__ void cp_tile(uint32_t smDst, const bf16* __restrict__ g,
                                        size_t row0, int K, int kt, int tid) {
    const char* gb = (const char*)(g + row0 * (size_t)K + (size_t)kt * KC);
    size_t pitchG = (size_t)K * 2;
    int row = tid >> 1, c = (tid & 1) * 16;
    CP_ASYNC16(smDst + (uint32_t)(row * SPITCH + c), gb + (size_t)row * pitchG + c);
}

__device__ __forceinline__ void mma_body(const bf16* __restrict__ Ah,
                                         const bf16* __restrict__ Al, int K,
                                         const bf16* __restrict__ Bh,
                                         const bf16* __restrict__ Bl,
                                         const float* __restrict__ bias,
                                         float* __restrict__ C) {
    __shared__ __align__(16) char smem[2 * STAGE_B];
    uint32_t sb = smem_to_u32(smem);
    int tid = threadIdx.x;
    int wid = tid >> 5, lane = tid & 31;
    int wm = wid & 1, wn = wid >> 1;
    size_t rowBase = (size_t)blockIdx.y * 128;
    size_t colBase = (size_t)blockIdx.x * 128;
    int nc = K / KC;

    float acc[4][4][4];
#pragma unroll
    for (int a = 0; a < 4; a++)
#pragma unroll
        for (int b = 0; b < 4; b++)
#pragma unroll
            for (int q = 0; q < 4; q++) acc[a][b][q] = 0.f;

    uint32_t kbyte = (uint32_t)((lane >> 4) * 16);
    uint32_t aOff = (uint32_t)((wm * 64 + (lane & 15)) * SPITCH) + kbyte;
    uint32_t bOff = (uint32_t)((wn * 32 + (lane & 15)) * SPITCH) + kbyte;

    {
        uint32_t st = sb;
        cp_tile(st + 0 * TILE_SB, Ah, rowBase, K, 0, tid);
        cp_tile(st + 1 * TILE_SB, Al, rowBase, K, 0, tid);
        cp_tile(st + 2 * TILE_SB, Bh, colBase, K, 0, tid);
        cp_tile(st + 3 * TILE_SB, Bl, colBase, K, 0, tid);
        CP_COMMIT();
    }

    for (int c = 0; c < nc; c++) {
        if (c + 1 < nc) {
            uint32_t st = sb + ((c + 1) & 1) * STAGE_B;
            cp_tile(st + 0 * TILE_SB, Ah, rowBase, K, c + 1, tid);
            cp_tile(st + 1 * TILE_SB, Al, rowBase, K, c + 1, tid);
            cp_tile(st + 2 * TILE_SB, Bh, colBase, K, c + 1, tid);
            cp_tile(st + 3 * TILE_SB, Bl, colBase, K, c + 1, tid);
            CP_COMMIT();
            CP_WAIT1();
        } else {
            CP_WAIT0();
        }
        __syncthreads();

        uint32_t st = sb + (c & 1) * STAGE_B;
        uint32_t ahB = st + 0 * TILE_SB + aOff;
        uint32_t alB = st + 1 * TILE_SB + aOff;
        uint32_t bhB = st + 2 * TILE_SB + bOff;
        uint32_t blB = st + 3 * TILE_SB + bOff;

        uint32_t ah[4][4], al[4][4], bh[2][4], bl[2][4];
#pragma unroll
        for (int mt = 0; mt < 4; mt++) {
            LDSM_X4(ah[mt][0], ah[mt][1], ah[mt][2], ah[mt][3], ahB + mt * 16 * SPITCH);
            LDSM_X4(al[mt][0], al[mt][1], al[mt][2], al[mt][3], alB + mt * 16 * SPITCH);
        }
#pragma unroll
        for (int p = 0; p < 2; p++) {
            LDSM_X4(bh[p][0], bh[p][1], bh[p][2], bh[p][3], bhB + p * 16 * SPITCH);
            LDSM_X4(bl[p][0], bl[p][1], bl[p][2], bl[p][3], blB + p * 16 * SPITCH);
        }
#pragma unroll
        for (int mt = 0; mt < 4; mt++)
#pragma unroll
            for (int nt = 0; nt < 4; nt++) {
                int p = nt >> 1, q = nt & 1;
                MMA_BF16(acc[mt][nt], ah[mt][0], ah[mt][1], ah[mt][2], ah[mt][3],
                         bh[p][q], bh[p][q + 2]);
                MMA_BF16(acc[mt][nt], ah[mt][0], ah[mt][1], ah[mt][2], ah[mt][3],
                         bl[p][q], bl[p][q + 2]);
                MMA_BF16(acc[mt][nt], al[mt][0], al[mt][1], al[mt][2], al[mt][3],
                         bh[p][q], bh[p][q + 2]);
            }
        __syncthreads();
    }

#pragma unroll
    for (int mt = 0; mt < 4; mt++) {
        size_t row = rowBase + wm * 64 + mt * 16 + (lane >> 2);
#pragma unroll
        for (int nt = 0; nt < 4; nt++) {
            size_t col = colBase + wn * 32 + nt * 8 + (lane & 3) * 2;
            float b0 = bias[col], b1 = bias[col + 1];
            *(float2*)(C + row * HC + col) =
                make_float2(acc[mt][nt][0] + b0, acc[mt][nt][1] + b1);
            *(float2*)(C + (row + 8) * HC + col) =
                make_float2(acc[mt][nt][2] + b0, acc[mt][nt][3] + b1);
        }
    }
}

__global__ __launch_bounds__(256, 2) void k_mma_xl1(const float* bias) {
    mma_body(g_xs_hi, g_xs_lo, FF, g_wl_hi, g_wl_lo, bias, g_xl1);
}
__global__ __launch_bounds__(256, 2) void k_mma_xr1(const float* bias) {
    mma_body(g_xs_hi, g_xs_lo, FF, g_wr_hi, g_wr_lo, bias, g_xr1);
}
__global__ __launch_bounds__(256, 2) void k_mma_xl2(const float* bias) {
    mma_body(g_hs_hi, g_hs_lo, HC, g_wl_hi, g_wl_lo, bias, g_xl2);
}
__global__ __launch_bounds__(256, 2) void k_mma_xr2(const float* bias) {
    mma_body(g_hs_hi, g_hs_lo, HC, g_wr_hi, g_wr_lo, bias, g_xr2);
}

// ---------------- HMMA verification: warp-parallel (one sample per warp) ----------------
__global__ void k_check(const float* __restrict__ A, const float* __restrict__ W,
                        const float* __restrict__ bias) {
    int wid = threadIdx.x >> 5, lane = threadIdx.x & 31;
    int t = blockIdx.x * 8 + wid;              // 0..255
    int row = (t * 64) & (NN - 1);
    int col = (t * 37) & (HC - 1);
    float acc = 0.f;
    for (int k = lane; k < FF; k += 32)
        acc += A[(size_t)row * FF + k] * W[(size_t)k * HC + col];
#pragma unroll
    for (int o = 16; o; o >>= 1) acc += __shfl_xor_sync(~0u, acc, o);
    if (lane == 0) {
        acc += bias[col];
        float got = g_xl1[(size_t)row * HC + col];
        if (fabsf(got - acc) > 2e-3f * (fabsf(acc) + 0.1f)) atomicExch(&g_bad, 1);
    }
}

// ---------------- fallback fp32 GEMM (proven), runs only if g_bad ----------------
__device__ __forceinline__ void sgemm_body(const float* __restrict__ A,
                                           const float* __restrict__ B,
                                           const float* __restrict__ bias,
                                           float* __restrict__ C, int K) {
    const int BM = 128, BK = 8;
    __shared__ __align__(16) float As2[BK][2 * BM];
    __shared__ __align__(16) float Bs[BK][128];
    int tid = threadIdx.x;
    int ty = tid >> 4, tx = tid & 15;
    int rowBase = blockIdx.y * BM;
    int colBase = blockIdx.x * 128;

    int arow = tid >> 1;
    int acol = (tid & 1) * 4;
    int brow = tid >> 5;
    int bcol = (tid & 31) * 4;

    const float* Ap = A + (size_t)(rowBase + arow) * K + acol;
    const float* Bp = B + (size_t)brow * HC + colBase + bcol;

    unsigned long long acc[8][4];
#pragma unroll
    for (int i = 0; i < 8; i++)
#pragma unroll
        for (int j = 0; j < 4; j++) acc[i][j] = 0ull;

    for (int kt = 0; kt < K; kt += BK) {
        float4 av = *(const float4*)(Ap + kt);
        float4 bv = *(const float4*)(Bp + (size_t)kt * HC);
        *(float2*)&As2[acol + 0][2 * arow] = make_float2(av.x, av.x);
        *(float2*)&As2[acol + 1][2 * arow] = make_float2(av.y, av.y);
        *(float2*)&As2[acol + 2][2 * arow] = make_float2(av.z, av.z);
        *(float2*)&As2[acol + 3][2 * arow] = make_float2(av.w, av.w);
        *(float4*)&Bs[brow][bcol] = bv;
        __syncthreads();
#pragma unroll
        for (int k = 0; k < BK; k++) {
            unsigned long long aP[8], bP[4];
            const unsigned long long* ap = (const unsigned long long*)&As2[k][ty * 16];
            const unsigned long long* bp = (const unsigned long long*)&Bs[k][tx * 8];
#pragma unroll
            for (int i = 0; i < 8; i++) aP[i] = ap[i];
#pragma unroll
            for (int j = 0; j < 4; j++) bP[j] = bp[j];
#pragma unroll
            for (int i = 0; i < 8; i++)
#pragma unroll
                for (int j = 0; j < 4; j++)
                    fma2(acc[i][j], aP[i], bP[j]);
        }
        __syncthreads();
    }

#pragma unroll
    for (int i = 0; i < 8; i++) {
        int row = rowBase + ty * 8 + i;
        float* cp = C + (size_t)row * HC + colBase + tx * 8;
#pragma unroll
        for (int j = 0; j < 4; j++) {
            float2 v = unpack2(acc[i][j]);
            int col = colBase + tx * 8 + j * 2;
            v.x += bias[col];
            v.y += bias[col + 1];
            *(float2*)(cp + j * 2) = v;
        }
    }
}
__global__ __launch_bounds__(256) void k_fb_xl1(const float* A, const float* W, const float* b) {
    if (!g_bad) return;
    sgemm_body(A, W, b, g_xl1, FF);
}
__global__ __launch_bounds__(256) void k_fb_xr1(const float* A, const float* W, const float* b) {
    if (!g_bad) return;
    sgemm_body(A, W, b, g_xr1, FF);
}
__global__ __launch_bounds__(256) void k_fb_xl2(const float* W, const float* b) {
    if (!g_bad) return;
    sgemm_body(g_h1, W, b, g_xl2, HC);
}
__global__ __launch_bounds__(256) void k_fb_xr2(const float* W, const float* b) {
    if (!g_bad) return;
    sgemm_body(g_h1, W, b, g_xr2, HC);
}

// ---------------- GATv2 edge pass: fused ep + SOFTWARE-PIPELINED loads ----------------
__device__ __forceinline__ void gat_edge_fused(const float* __restrict__ xl,
                                               const float* __restrict__ xr,
                                               const float* __restrict__ ea,
                                               const float* __restrict__ We,
                                               const float* __restrict__ att,
                                               const float* __restrict__ bias,
                                               float* __restrict__ out,
                                               bool concat) {
    __shared__ float sOut[HC];
    int tid = threadIdx.x;
    int n = blockIdx.x;

    // preload this thread's 4 columns of We (RR x 4 floats) as packed pairs
    unsigned long long we2[RR][2];
    unsigned long long self0 = 0ull, self1 = 0ull;
    const unsigned long long half2 = pack2(SELF_FILL, SELF_FILL);
#pragma unroll
    for (int k = 0; k < RR; k++) {
        float4 w = *(const float4*)&We[k * HC + tid * 4];
        we2[k][0] = pack2(w.x, w.y);
        we2[k][1] = pack2(w.z, w.w);
        fma2(self0, half2, we2[k][0]);
        fma2(self1, half2, we2[k][1]);
    }
    float4 attv = ((const float4*)att)[tid];
    float4 xr4 = ((const float4*)(xr + (size_t)n * HC))[tid];
    float2 selfa = unpack2(self0), selfb = unpack2(self1);

    float m = -1e30f, s = 0.f;
    float ax = 0.f, ay = 0.f, az = 0.f, aw = 0.f;
    int b = g_off[n], e = g_off[n + 1];

    // prime the pipeline: loads for edge b in flight
    int2 ce = g_csr[b];
    float4 xc = ((const float4*)(xl + (size_t)ce.x * HC))[tid];
    float4 c0 = {}, c1 = {}, c2 = {}, c3 = {};
    if (ce.y < NE) {
        const float4* er = (const float4*)(ea + (size_t)ce.y * RR);
        c0 = er[0]; c1 = er[1]; c2 = er[2]; c3 = er[3];
    }

    for (int i = b; i < e; i++) {
        // prefetch NEXT edge (csr + ea row + xl row) before computing current
        int2 nc2 = ce;
        float4 nx = {}, n0 = {}, n1 = {}, n2 = {}, n3 = {};
        if (i + 1 < e) {
            nc2 = g_csr[i + 1];
            nx = ((const float4*)(xl + (size_t)nc2.x * HC))[tid];
            if (nc2.y < NE) {
                const float4* er = (const float4*)(ea + (size_t)nc2.y * RR);
                n0 = er[0]; n1 = er[1]; n2 = er[2]; n3 = er[3];
            }
        }

        // compute current edge from prefetched registers
        float2 pa, pb;
        if (ce.y < NE) {
            float ev[RR] = {c0.x, c0.y, c0.z, c0.w, c1.x, c1.y, c1.z, c1.w,
                            c2.x, c2.y, c2.z, c2.w, c3.x, c3.y, c3.z, c3.w};
            unsigned long long p0 = 0ull, p1 = 0ull;
#pragma unroll
            for (int k = 0; k < RR; k++) {
                unsigned long long ee = pack2(ev[k], ev[k]);
                fma2(p0, ee, we2[k][0]);
                fma2(p1, ee, we2[k][1]);
            }
            pa = unpack2(p0); pb = unpack2(p1);
        } else {
            pa = selfa; pb = selfb;
        }
        float zx = xc.x + xr4.x + pa.x; zx = zx > 0.f ? zx : NEG_SLOPE * zx;
        float zy = xc.y + xr4.y + pa.y; zy = zy > 0.f ? zy : NEG_SLOPE * zy;
        float zz = xc.z + xr4.z + pb.x; zz = zz > 0.f ? zz : NEG_SLOPE * zz;
        float zw = xc.w + xr4.w + pb.y; zw = zw > 0.f ? zw : NEG_SLOPE * zw;
        float p = zx * attv.x + zy * attv.y + zz * attv.z + zw * attv.w;
        p += __shfl_xor_sync(~0u, p, 8);
        p += __shfl_xor_sync(~0u, p, 4);
        p += __shfl_xor_sync(~0u, p, 2);
        p += __shfl_xor_sync(~0u, p, 1);
        float mN = fmaxf(m, p);
        float sc = __expf(m - mN);
        float w  = __expf(p - mN);
        s  = s  * sc + w;
        ax = ax * sc + w * xc.x;
        ay = ay * sc + w * xc.y;
        az = az * sc + w * xc.z;
        aw = aw * sc + w * xc.w;
        m = mN;

        // rotate pipeline registers
        ce = nc2; xc = nx;
        c0 = n0; c1 = n1; c2 = n2; c3 = n3;
    }

    float inv = 1.f / (s + 1e-16f);
    if (concat) {
        float4 o = make_float4(ax * inv + bias[tid * 4 + 0], ay * inv + bias[tid * 4 + 1],
                               az * inv + bias[tid * 4 + 2], aw * inv + bias[tid * 4 + 3]);
        size_t base = (size_t)n * HC + tid * 4;
        ((float4*)(out + (size_t)n * HC))[tid] = o;   // g_h1 (fallback path input)
        bf16 h0, l0, h1, l1, h2, l2, h3, l3;
        split1(o.x, h0, l0); split1(o.y, h1, l1);
        split1(o.z, h2, l2); split1(o.w, h3, l3);
        *(uint2*)&g_hs_hi[base] = make_uint2(pkbf(h0, h1), pkbf(h2, h3));
        *(uint2*)&g_hs_lo[base] = make_uint2(pkbf(l0, l1), pkbf(l2, l3));
    } else {
        sOut[tid * 4 + 0] = ax * inv; sOut[tid * 4 + 1] = ay * inv;
        sOut[tid * 4 + 2] = az * inv; sOut[tid * 4 + 3] = aw * inv;
        __syncthreads();
        if (tid < CC) {
            float acc = 0.f;
#pragma unroll
            for (int h = 0; h < HH; h++) acc += sOut[h * CC + tid];
            out[(size_t)n * CC + tid] = acc * (1.f / HH) + bias[tid];
        }
    }
}
__global__ __launch_bounds__(128) void k_edge1(const float* ea, const float* We,
                                               const float* att, const float* bias) {
    gat_edge_fused(g_xl1, g_xr1, ea, We, att, bias, g_h1, true);
}
__global__ __launch_bounds__(128) void k_edge2(const float* ea, const float* We,
                                               const float* att, const float* bias,
                                               float* out) {
    gat_edge_fused(g_xl2, g_xr2, ea, We, att, bias, out, false);
}

// ---------------- launch ----------------
extern "C" void kernel_launch(void* const* d_in, const int* in_sizes, int n_in,
                              void* d_out, int out_size) {
    const float* x     = (const float*)d_in[0];
    const void*  ei    = d_in[1];
    const float* ea    = (const float*)d_in[2];
    const float* Wl1   = (const float*)d_in[3];
    const float* bl1   = (const float*)d_in[4];
    const float* Wr1   = (const float*)d_in[5];
    const float* br1   = (const float*)d_in[6];
    const float* We1   = (const float*)d_in[7];
    const float* att1  = (const float*)d_in[8];
    const float* bias1 = (const float*)d_in[9];
    const float* Wl2   = (const float*)d_in[10];
    const float* bl2   = (const float*)d_in[11];
    const float* Wr2   = (const float*)d_in[12];
    const float* br2   = (const float*)d_in[13];
    const float* We2   = (const float*)d_in[14];
    const float* att2  = (const float*)d_in[15];
    const float* bias2 = (const float*)d_in[16];
    float* out = (float*)d_out;

    dim3 gn(HC / 128, NN / 128);
    dim3 wtb(32, 8);
    dim3 wt1(FF / 32, HC / 32);
    dim3 wt2(HC / 32, HC / 32);

    // launch #4 is the HMMA GEMM (ncu -s 5 -c 1 slot)
    k_detect<<<1, 256>>>((const long long*)ei);                 // 1
    k_split_x<<<(NN * FF + 255) / 256, 256>>>(x);               // 2
    k_wT_both<<<wt1, wtb>>>(Wl1, Wr1, FF);                      // 3
    k_mma_xl1<<<gn, 256>>>(bl1);                                // 4  <- profile me
    k_init_deg<<<NN / 256, 256>>>();                            // 5
    k_convert<<<NE / 256, 256>>>(ei);                           // 6
    k_scan<<<1, 1024>>>();                                      // 7
    k_scatter<<<(NEP + 255) / 256, 256>>>();                    // 8
    k_mma_xr1<<<gn, 256>>>(br1);                                // 9
    k_check<<<32, 256>>>(x, Wl1, bl1);                          // 10
    k_fb_xl1<<<gn, 256>>>(x, Wl1, bl1);                         // 11
    k_fb_xr1<<<gn, 256>>>(x, Wr1, br1);                         // 12
    k_edge1<<<NN, 128>>>(ea, We1, att1, bias1);                 // 13

    k_wT_both<<<wt2, wtb>>>(Wl2, Wr2, HC);                      // 14
    k_mma_xl2<<<gn, 256>>>(bl2);                                // 15
    k_mma_xr2<<<gn, 256>>>(br2);                                // 16
    k_fb_xl2<<<gn, 256>>>(Wl2, bl2);                            // 17
    k_fb_xr2<<<gn, 256>>>(Wr2, br2);                            // 18
    k_edge2<<<NN, 128>>>(ea, We2, att2, bias2, out);            // 19
}

// round 13
// speedup vs baseline: 1.1395x; 1.1395x over previous
#include <cuda_runtime.h>
#include <cuda_bf16.h>
#include <cstdint>

typedef __nv_bfloat16 bf16;

// ---------------- problem constants ----------------
#define NN   16384
#define FF   128
#define RR   16
#define HH   8
#define CC   64
#define HC   512
#define NE   163840
#define NEP  180224          // NE + NN self loops
#define NEG_SLOPE 0.2f
#define SELF_FILL 0.5f

// ---------------- device scratch (only ever touched from device code) ----------------
__device__ int   g_is64;
__device__ int   g_bad;
__device__ int   g_src32[NE];
__device__ int   g_dst32[NE];
__device__ int   g_deg[NN];
__device__ int   g_off[NN + 1];
__device__ int   g_fill[NN];
__device__ int   g_csr_src[NEP];
__device__ int   g_csr_eid[NEP];
__device__ float g_xl1[(size_t)NN * HC];
__device__ float g_xr1[(size_t)NN * HC];
__device__ float g_h1 [(size_t)NN * HC];
__device__ float g_xl2[(size_t)NN * HC];
__device__ float g_xr2[(size_t)NN * HC];
__device__ __align__(16) bf16 g_xs_hi[(size_t)NN * FF];
__device__ __align__(16) bf16 g_xs_lo[(size_t)NN * FF];
__device__ __align__(16) bf16 g_hs_hi[(size_t)NN * HC];
__device__ __align__(16) bf16 g_hs_lo[(size_t)NN * HC];
__device__ __align__(16) bf16 g_wl_hi[HC * HC];
__device__ __align__(16) bf16 g_wl_lo[HC * HC];
__device__ __align__(16) bf16 g_wr_hi[HC * HC];
__device__ __align__(16) bf16 g_wr_lo[HC * HC];

// ---------------- asm helpers ----------------
#define LDSM_X4(r0, r1, r2, r3, a) \
    asm volatile("ldmatrix.sync.aligned.m8n8.x4.shared.b16 {%0,%1,%2,%3}, [%4];" \
                 : "=r"(r0), "=r"(r1), "=r"(r2), "=r"(r3) : "r"(a))

#define MMA_BF16(d, a0, a1, a2, a3, b0, b1) \
    asm volatile("mma.sync.aligned.m16n8k16.row.col.f32.bf16.bf16.f32 " \
                 "{%0,%1,%2,%3}, {%4,%5,%6,%7}, {%8,%9}, {%0,%1,%2,%3};" \
                 : "+f"((d)[0]), "+f"((d)[1]), "+f"((d)[2]), "+f"((d)[3]) \
                 : "r"(a0), "r"(a1), "r"(a2), "r"(a3), "r"(b0), "r"(b1))

#define CP_ASYNC16(dst, src) \
    asm volatile("cp.async.cg.shared.global [%0], [%1], 16;" :: "r"(dst), "l"(src))
#define CP_COMMIT()  asm volatile("cp.async.commit_group;" ::: "memory")
#define CP_WAIT0()   asm volatile("cp.async.wait_group 0;" ::: "memory")
#define CP_WAIT1()   asm volatile("cp.async.wait_group 1;" ::: "memory")

__device__ __forceinline__ uint32_t smem_to_u32(const void* p) {
    uint32_t a;
    asm("{ .reg .u64 t; cvta.to.shared.u64 t, %1; cvt.u32.u64 %0, t; }" : "=r"(a) : "l"(p));
    return a;
}
__device__ __forceinline__ void fma2(unsigned long long& d, unsigned long long a,
                                     unsigned long long b) {
    asm("fma.rn.f32x2 %0, %1, %2, %0;" : "+l"(d) : "l"(a), "l"(b));
}
__device__ __forceinline__ unsigned long long pack2(float a, float b) {
    unsigned long long r;
    asm("mov.b64 %0, {%1, %2};" : "=l"(r) : "f"(a), "f"(b));
    return r;
}
__device__ __forceinline__ float2 unpack2(unsigned long long v) {
    float2 f;
    asm("mov.b64 {%0, %1}, %2;" : "=f"(f.x), "=f"(f.y) : "l"(v));
    return f;
}
__device__ __forceinline__ uint32_t pkbf(bf16 a, bf16 b) {
    uint16_t ua = *(uint16_t*)&a, ub = *(uint16_t*)&b;
    return (uint32_t)ua | ((uint32_t)ub << 16);
}

// ---------------- dtype detect / convert / CSR ----------------
__global__ void k_detect(const long long* ei) {
    __shared__ int ok;
    if (threadIdx.x == 0) ok = 1;
    __syncthreads();
    for (int i = threadIdx.x; i < 2048; i += blockDim.x) {
        long long v = ei[i];
        if (v < 0 || v >= NN) ok = 0;
    }
    __syncthreads();
    if (threadIdx.x == 0) g_is64 = ok;
}
__global__ void k_init_deg() {
    int n = blockIdx.x * blockDim.x + threadIdx.x;
    if (n < NN) g_deg[n] = 1;
    if (n == 0) g_bad = 0;
}
__global__ void k_convert(const void* ei) {
    int e = blockIdx.x * blockDim.x + threadIdx.x;
    if (e >= NE) return;
    int s, d;
    if (g_is64) {
        const long long* p = (const long long*)ei;
        s = (int)p[e]; d = (int)p[NE + e];
    } else {
        const int* p = (const int*)ei;
        s = p[e]; d = p[NE + e];
    }
    g_src32[e] = s; g_dst32[e] = d;
    atomicAdd(&g_deg[d], 1);
}
__global__ void k_scan() {
    const int PER = NN / 1024;
    int t = threadIdx.x, lane = t & 31, warp = t >> 5;
    int base = t * PER;
    int loc[PER]; int run = 0;
#pragma unroll
    for (int i = 0; i < PER; i++) { loc[i] = run; run += g_deg[base + i]; }
    int v = run;
#pragma unroll
    for (int o = 1; o < 32; o <<= 1) { int u = __shfl_up_sync(~0u, v, o); if (lane >= o) v += u; }
    __shared__ int ws[32];
    if (lane == 31) ws[warp] = v;
    __syncthreads();
    if (warp == 0) {
        int w = ws[lane];
#pragma unroll
        for (int o = 1; o < 32; o <<= 1) { int u = __shfl_up_sync(~0u, w, o); if (lane >= o) w += u; }
        ws[lane] = w;
    }
    __syncthreads();
    int excl = (warp ? ws[warp - 1] : 0) + (v - run);
#pragma unroll
    for (int i = 0; i < PER; i++) { int o = excl + loc[i]; g_off[base + i] = o; g_fill[base + i] = o; }
    if (t == 1023) g_off[NN] = excl + run;
}
__global__ void k_scatter() {
    int e = blockIdx.x * blockDim.x + threadIdx.x;
    if (e >= NEP) return;
    int s = (e < NE) ? g_src32[e] : (e - NE);
    int d = (e < NE) ? g_dst32[e] : (e - NE);
    int pos = atomicAdd(&g_fill[d], 1);
    g_csr_src[pos] = s; g_csr_eid[pos] = e;
}
__global__ void k_sort() {
    int n = blockIdx.x * blockDim.x + threadIdx.x;
    if (n >= NN) return;
    int b = g_off[n], e = g_off[n + 1];
    for (int i = b + 1; i < e; i++) {
        int ke = g_csr_eid[i], ks = g_csr_src[i];
        int j = i - 1;
        while (j >= b && g_csr_eid[j] > ke) {
            g_csr_eid[j + 1] = g_csr_eid[j]; g_csr_src[j + 1] = g_csr_src[j]; j--;
        }
        g_csr_eid[j + 1] = ke; g_csr_src[j + 1] = ks;
    }
}

// ---------------- split / transpose (globals bound in device code) ----------------
__device__ __forceinline__ void split1(float v, bf16& h, bf16& l) {
    h = __float2bfloat16(v);
    l = __float2bfloat16(v - __bfloat162float(h));
}
__global__ void k_split_x(const float* __restrict__ src) {
    int i = blockIdx.x * blockDim.x + threadIdx.x;
    if (i >= NN * FF) return;
    split1(src[i], g_xs_hi[i], g_xs_lo[i]);
}
__device__ __forceinline__ void wT_body(const float* __restrict__ W, int K,
                                        bf16* __restrict__ hi, bf16* __restrict__ lo) {
    int i = blockIdx.x * blockDim.x + threadIdx.x;
    if (i >= HC * K) return;
    int n = i / K, k = i % K;
    split1(W[(size_t)k * HC + n], hi[i], lo[i]);
}
__global__ void k_wT_l(const float* __restrict__ W, int K) { wT_body(W, K, g_wl_hi, g_wl_lo); }
__global__ void k_wT_r(const float* __restrict__ W, int K) { wT_body(W, K, g_wr_hi, g_wr_lo); }

// ---------------- bf16 HMMA GEMM: cp.async double-buffered, KC=16, pitch 48 ----------------
#define KC       16
#define SPITCH   48
#define TILE_SB  (128 * SPITCH)     // 6144
#define STAGE_B  (4 * TILE_SB)      // 24576
// 2 stages = 49152 bytes static shared

__device__ __forceinline__ void cp_tile(uint32_t smDst, const bf16* __restrict__ g,
                                        size_t row0, int K, int kt, int tid) {
    const char* gb = (const char*)(g + row0 * (size_t)K + (size_t)kt * KC);
    size_t pitchG = (size_t)K * 2;
    int row = tid >> 1, c = (tid & 1) * 16;   // 128 rows x 32B
    CP_ASYNC16(smDst + (uint32_t)(row * SPITCH + c), gb + (size_t)row * pitchG + c);
}

__device__ __forceinline__ void mma_body(const bf16* __restrict__ Ah,
                                         const bf16* __restrict__ Al, int K,
                                         const bf16* __restrict__ Bh,
                                         const bf16* __restrict__ Bl,
                                         const float* __restrict__ bias,
                                         float* __restrict__ C) {
    __shared__ __align__(16) char smem[2 * STAGE_B];
    uint32_t sb = smem_to_u32(smem);
    int tid = threadIdx.x;
    int wid = tid >> 5, lane = tid & 31;
    int wm = wid & 1, wn = wid >> 1;
    size_t rowBase = (size_t)blockIdx.y * 128;
    size_t colBase = (size_t)blockIdx.x * 128;
    int nc = K / KC;

    float acc[4][4][4];
#pragma unroll
    for (int a = 0; a < 4; a++)
#pragma unroll
        for (int b = 0; b < 4; b++)
#pragma unroll
            for (int q = 0; q < 4; q++) acc[a][b][q] = 0.f;

    uint32_t kbyte = (uint32_t)((lane >> 4) * 16);
    uint32_t aOff = (uint32_t)((wm * 64 + (lane & 15)) * SPITCH) + kbyte;
    uint32_t bOff = (uint32_t)((wn * 32 + (lane & 15)) * SPITCH) + kbyte;

    // prologue: stage 0
    {
        uint32_t st = sb;
        cp_tile(st + 0 * TILE_SB, Ah, rowBase, K, 0, tid);
        cp_tile(st + 1 * TILE_SB, Al, rowBase, K, 0, tid);
        cp_tile(st + 2 * TILE_SB, Bh, colBase, K, 0, tid);
        cp_tile(st + 3 * TILE_SB, Bl, colBase, K, 0, tid);
        CP_COMMIT();
    }

    for (int c = 0; c < nc; c++) {
        if (c + 1 < nc) {
            uint32_t st = sb + ((c + 1) & 1) * STAGE_B;
            cp_tile(st + 0 * TILE_SB, Ah, rowBase, K, c + 1, tid);
            cp_tile(st + 1 * TILE_SB, Al, rowBase, K, c + 1, tid);
            cp_tile(st + 2 * TILE_SB, Bh, colBase, K, c + 1, tid);
            cp_tile(st + 3 * TILE_SB, Bl, colBase, K, c + 1, tid);
            CP_COMMIT();
            CP_WAIT1();
        } else {
            CP_WAIT0();
        }
        __syncthreads();

        uint32_t st = sb + (c & 1) * STAGE_B;
        uint32_t ahB = st + 0 * TILE_SB + aOff;
        uint32_t alB = st + 1 * TILE_SB + aOff;
        uint32_t bhB = st + 2 * TILE_SB + bOff;
        uint32_t blB = st + 3 * TILE_SB + bOff;

        uint32_t ah[4][4], al[4][4], bh[2][4], bl[2][4];
#pragma unroll
        for (int mt = 0; mt < 4; mt++) {
            LDSM_X4(ah[mt][0], ah[mt][1], ah[mt][2], ah[mt][3], ahB + mt * 16 * SPITCH);
            LDSM_X4(al[mt][0], al[mt][1], al[mt][2], al[mt][3], alB + mt * 16 * SPITCH);
        }
#pragma unroll
        for (int p = 0; p < 2; p++) {
            LDSM_X4(bh[p][0], bh[p][1], bh[p][2], bh[p][3], bhB + p * 16 * SPITCH);
            LDSM_X4(bl[p][0], bl[p][1], bl[p][2], bl[p][3], blB + p * 16 * SPITCH);
        }
#pragma unroll
        for (int mt = 0; mt < 4; mt++)
#pragma unroll
            for (int nt = 0; nt < 4; nt++) {
                int p = nt >> 1, q = nt & 1;
                MMA_BF16(acc[mt][nt], ah[mt][0], ah[mt][1], ah[mt][2], ah[mt][3],
                         bh[p][q], bh[p][q + 2]);
                MMA_BF16(acc[mt][nt], ah[mt][0], ah[mt][1], ah[mt][2], ah[mt][3],
                         bl[p][q], bl[p][q + 2]);
                MMA_BF16(acc[mt][nt], al[mt][0], al[mt][1], al[mt][2], al[mt][3],
                         bh[p][q], bh[p][q + 2]);
            }
        __syncthreads();
    }

#pragma unroll
    for (int mt = 0; mt < 4; mt++) {
        size_t row = rowBase + wm * 64 + mt * 16 + (lane >> 2);
#pragma unroll
        for (int nt = 0; nt < 4; nt++) {
            size_t col = colBase + wn * 32 + nt * 8 + (lane & 3) * 2;
            float b0 = bias[col], b1 = bias[col + 1];
            *(float2*)(C + row * HC + col) =
                make_float2(acc[mt][nt][0] + b0, acc[mt][nt][1] + b1);
            *(float2*)(C + (row + 8) * HC + col) =
                make_float2(acc[mt][nt][2] + b0, acc[mt][nt][3] + b1);
        }
    }
}

__global__ __launch_bounds__(256, 2) void k_mma_xl1(const float* bias) {
    mma_body(g_xs_hi, g_xs_lo, FF, g_wl_hi, g_wl_lo, bias, g_xl1);
}
__global__ __launch_bounds__(256, 2) void k_mma_xr1(const float* bias) {
    mma_body(g_xs_hi, g_xs_lo, FF, g_wr_hi, g_wr_lo, bias, g_xr1);
}
__global__ __launch_bounds__(256, 2) void k_mma_xl2(const float* bias) {
    mma_body(g_hs_hi, g_hs_lo, HC, g_wl_hi, g_wl_lo, bias, g_xl2);
}
__global__ __launch_bounds__(256, 2) void k_mma_xr2(const float* bias) {
    mma_body(g_hs_hi, g_hs_lo, HC, g_wr_hi, g_wr_lo, bias, g_xr2);
}

// ---------------- HMMA verification: warp-parallel (one sample per warp) ----------------
// grid 32 x 256 threads: 8 warps/block, sample = blockIdx.x*8 + warp; lanes split K.
__global__ void k_check(const float* __restrict__ A, const float* __restrict__ W,
                        const float* __restrict__ bias) {
    int wid = threadIdx.x >> 5, lane = threadIdx.x & 31;
    int t = blockIdx.x * 8 + wid;              // 0..255
    int row = (t * 64) & (NN - 1);
    int col = (t * 37) & (HC - 1);
    float acc = 0.f;
    for (int k = lane; k < FF; k += 32)
        acc += A[(size_t)row * FF + k] * W[(size_t)k * HC + col];
#pragma unroll
    for (int o = 16; o; o >>= 1) acc += __shfl_xor_sync(~0u, acc, o);
    if (lane == 0) {
        acc += bias[col];
        float got = g_xl1[(size_t)row * HC + col];
        if (fabsf(got - acc) > 2e-3f * (fabsf(acc) + 0.1f)) atomicExch(&g_bad, 1);
    }
}

// ---------------- fallback fp32 GEMM (proven), runs only if g_bad ----------------
__device__ __forceinline__ void sgemm_body(const float* __restrict__ A,
                                           const float* __restrict__ B,
                                           const float* __restrict__ bias,
                                           float* __restrict__ C, int K) {
    const int BM = 128, BK = 8;
    __shared__ __align__(16) float As2[BK][2 * BM];
    __shared__ __align__(16) float Bs[BK][128];
    int tid = threadIdx.x;
    int ty = tid >> 4, tx = tid & 15;
    int rowBase = blockIdx.y * BM;
    int colBase = blockIdx.x * 128;

    int arow = tid >> 1;
    int acol = (tid & 1) * 4;
    int brow = tid >> 5;
    int bcol = (tid & 31) * 4;

    const float* Ap = A + (size_t)(rowBase + arow) * K + acol;
    const float* Bp = B + (size_t)brow * HC + colBase + bcol;

    unsigned long long acc[8][4];
#pragma unroll
    for (int i = 0; i < 8; i++)
#pragma unroll
        for (int j = 0; j < 4; j++) acc[i][j] = 0ull;

    for (int kt = 0; kt < K; kt += BK) {
        float4 av = *(const float4*)(Ap + kt);
        float4 bv = *(const float4*)(Bp + (size_t)kt * HC);
        *(float2*)&As2[acol + 0][2 * arow] = make_float2(av.x, av.x);
        *(float2*)&As2[acol + 1][2 * arow] = make_float2(av.y, av.y);
        *(float2*)&As2[acol + 2][2 * arow] = make_float2(av.z, av.z);
        *(float2*)&As2[acol + 3][2 * arow] = make_float2(av.w, av.w);
        *(float4*)&Bs[brow][bcol] = bv;
        __syncthreads();
#pragma unroll
        for (int k = 0; k < BK; k++) {
            unsigned long long aP[8], bP[4];
            const unsigned long long* ap = (const unsigned long long*)&As2[k][ty * 16];
            const unsigned long long* bp = (const unsigned long long*)&Bs[k][tx * 8];
#pragma unroll
            for (int i = 0; i < 8; i++) aP[i] = ap[i];
#pragma unroll
            for (int j = 0; j < 4; j++) bP[j] = bp[j];
#pragma unroll
            for (int i = 0; i < 8; i++)
#pragma unroll
                for (int j = 0; j < 4; j++)
                    fma2(acc[i][j], aP[i], bP[j]);
        }
        __syncthreads();
    }

#pragma unroll
    for (int i = 0; i < 8; i++) {
        int row = rowBase + ty * 8 + i;
        float* cp = C + (size_t)row * HC + colBase + tx * 8;
#pragma unroll
        for (int j = 0; j < 4; j++) {
            float2 v = unpack2(acc[i][j]);
            int col = colBase + tx * 8 + j * 2;
            v.x += bias[col];
            v.y += bias[col + 1];
            *(float2*)(cp + j * 2) = v;
        }
    }
}
__global__ __launch_bounds__(256) void k_fb_xl1(const float* A, const float* W, const float* b) {
    if (!g_bad) return;
    sgemm_body(A, W, b, g_xl1, FF);
}
__global__ __launch_bounds__(256) void k_fb_xr1(const float* A, const float* W, const float* b) {
    if (!g_bad) return;
    sgemm_body(A, W, b, g_xr1, FF);
}
__global__ __launch_bounds__(256) void k_fb_xl2(const float* W, const float* b) {
    if (!g_bad) return;
    sgemm_body(g_h1, W, b, g_xl2, HC);
}
__global__ __launch_bounds__(256) void k_fb_xr2(const float* W, const float* b) {
    if (!g_bad) return;
    sgemm_body(g_h1, W, b, g_xr2, HC);
}

// ---------------- GATv2 edge pass with FUSED edge-feature transform (round-7) ----------
__device__ __forceinline__ void gat_edge_fused(const float* __restrict__ xl,
                                               const float* __restrict__ xr,
                                               const float* __restrict__ ea,
                                               const float* __restrict__ We,
                                               const float* __restrict__ att,
                                               const float* __restrict__ bias,
                                               float* __restrict__ out,
                                               bool concat) {
    __shared__ float sOut[HC];
    int tid = threadIdx.x;
    int n = blockIdx.x;

    // preload this thread's 4 columns of We (RR x 4 floats) as packed pairs
    unsigned long long we2[RR][2];
    unsigned long long self0 = 0ull, self1 = 0ull;
    const unsigned long long half2 = pack2(SELF_FILL, SELF_FILL);
#pragma unroll
    for (int k = 0; k < RR; k++) {
        float4 w = *(const float4*)&We[k * HC + tid * 4];
        we2[k][0] = pack2(w.x, w.y);
        we2[k][1] = pack2(w.z, w.w);
        fma2(self0, half2, we2[k][0]);     // self-loop ep (constant per column)
        fma2(self1, half2, we2[k][1]);
    }

    float4 attv = ((const float4*)att)[tid];
    float4 xr4 = ((const float4*)(xr + (size_t)n * HC))[tid];

    float m = -1e30f, s = 0.f;
    float ax = 0.f, ay = 0.f, az = 0.f, aw = 0.f;
    int b = g_off[n], e = g_off[n + 1];
    for (int i = b; i < e; i++) {
        int src = g_csr_src[i];
        int eid = g_csr_eid[i];
        float4 xl4 = ((const float4*)(xl + (size_t)src * HC))[tid];
        float2 pa, pb;
        if (eid < NE) {
            const float4* er = (const float4*)(ea + (size_t)eid * RR);
            float4 e0 = er[0], e1 = er[1], e2 = er[2], e3 = er[3];
            float ev[RR] = {e0.x, e0.y, e0.z, e0.w, e1.x, e1.y, e1.z, e1.w,
                            e2.x, e2.y, e2.z, e2.w, e3.x, e3.y, e3.z, e3.w};
            unsigned long long p0 = 0ull, p1 = 0ull;
#pragma unroll
            for (int k = 0; k < RR; k++) {
                unsigned long long ee = pack2(ev[k], ev[k]);
                fma2(p0, ee, we2[k][0]);
                fma2(p1, ee, we2[k][1]);
            }
            pa = unpack2(p0); pb = unpack2(p1);
        } else {
            pa = unpack2(self0); pb = unpack2(self1);
        }
        float zx = xl4.x + xr4.x + pa.x; zx = zx > 0.f ? zx : NEG_SLOPE * zx;
        float zy = xl4.y + xr4.y + pa.y; zy = zy > 0.f ? zy : NEG_SLOPE * zy;
        float zz = xl4.z + xr4.z + pb.x; zz = zz > 0.f ? zz : NEG_SLOPE * zz;
        float zw = xl4.w + xr4.w + pb.y; zw = zw > 0.f ? zw : NEG_SLOPE * zw;
        float p = zx * attv.x + zy * attv.y + zz * attv.z + zw * attv.w;
        p += __shfl_xor_sync(~0u, p, 8);
        p += __shfl_xor_sync(~0u, p, 4);
        p += __shfl_xor_sync(~0u, p, 2);
        p += __shfl_xor_sync(~0u, p, 1);
        float mN = fmaxf(m, p);
        float sc = __expf(m - mN);
        float w  = __expf(p - mN);
        s  = s  * sc + w;
        ax = ax * sc + w * xl4.x;
        ay = ay * sc + w * xl4.y;
        az = az * sc + w * xl4.z;
        aw = aw * sc + w * xl4.w;
        m = mN;
    }
    float inv = 1.f / (s + 1e-16f);
    if (concat) {
        float4 o = make_float4(ax * inv + bias[tid * 4 + 0], ay * inv + bias[tid * 4 + 1],
                               az * inv + bias[tid * 4 + 2], aw * inv + bias[tid * 4 + 3]);
        size_t base = (size_t)n * HC + tid * 4;
        ((float4*)(out + (size_t)n * HC))[tid] = o;     // g_h1 (kept for fallback path)
        // fused bf16 split for the layer-2 GEMM input
        bf16 h0, l0, h1, l1, h2, l2, h3, l3;
        split1(o.x, h0, l0); split1(o.y, h1, l1);
        split1(o.z, h2, l2); split1(o.w, h3, l3);
        *(uint2*)&g_hs_hi[base] = make_uint2(pkbf(h0, h1), pkbf(h2, h3));
        *(uint2*)&g_hs_lo[base] = make_uint2(pkbf(l0, l1), pkbf(l2, l3));
    } else {
        sOut[tid * 4 + 0] = ax * inv; sOut[tid * 4 + 1] = ay * inv;
        sOut[tid * 4 + 2] = az * inv; sOut[tid * 4 + 3] = aw * inv;
        __syncthreads();
        if (tid < CC) {
            float acc = 0.f;
#pragma unroll
            for (int h = 0; h < HH; h++) acc += sOut[h * CC + tid];
            out[(size_t)n * CC + tid] = acc * (1.f / HH) + bias[tid];
        }
    }
}
__global__ __launch_bounds__(128) void k_edge1(const float* ea, const float* We,
                                               const float* att, const float* bias) {
    gat_edge_fused(g_xl1, g_xr1, ea, We, att, bias, g_h1, true);
}
__global__ __launch_bounds__(128) void k_edge2(const float* ea, const float* We,
                                               const float* att, const float* bias,
                                               float* out) {
    gat_edge_fused(g_xl2, g_xr2, ea, We, att, bias, out, false);
}

// ---------------- launch ----------------
extern "C" void kernel_launch(void* const* d_in, const int* in_sizes, int n_in,
                              void* d_out, int out_size) {
    const float* x     = (const float*)d_in[0];
    const void*  ei    = d_in[1];
    const float* ea    = (const float*)d_in[2];
    const float* Wl1   = (const float*)d_in[3];
    const float* bl1   = (const float*)d_in[4];
    const float* Wr1   = (const float*)d_in[5];
    const float* br1   = (const float*)d_in[6];
    const float* We1   = (const float*)d_in[7];
    const float* att1  = (const float*)d_in[8];
    const float* bias1 = (const float*)d_in[9];
    const float* Wl2   = (const float*)d_in[10];
    const float* bl2   = (const float*)d_in[11];
    const float* Wr2   = (const float*)d_in[12];
    const float* br2   = (const float*)d_in[13];
    const float* We2   = (const float*)d_in[14];
    const float* att2  = (const float*)d_in[15];
    const float* bias2 = (const float*)d_in[16];
    float* out = (float*)d_out;

    dim3 gn(HC / 128, NN / 128);

    // launch #4 is the HMMA GEMM (ncu -s 5 -c 1 slot)
    k_detect<<<1, 256>>>((const long long*)ei);                 // 1
    k_split_x<<<(NN * FF + 255) / 256, 256>>>(x);               // 2
    k_wT_l<<<(HC * FF + 255) / 256, 256>>>(Wl1, FF);            // 3
    k_mma_xl1<<<gn, 256>>>(bl1);                                // 4  <- profile me
    k_init_deg<<<NN / 256, 256>>>();                            // 5
    k_convert<<<NE / 256, 256>>>(ei);                           // 6
    k_scan<<<1, 1024>>>();                                      // 7
    k_scatter<<<(NEP + 255) / 256, 256>>>();                    // 8
    k_sort<<<(NN + 127) / 128, 128>>>();                        // 9
    k_wT_r<<<(HC * FF + 255) / 256, 256>>>(Wr1, FF);            // 10
    k_mma_xr1<<<gn, 256>>>(br1);                                // 11
    k_check<<<32, 256>>>(x, Wl1, bl1);                          // 12
    k_fb_xl1<<<gn, 256>>>(x, Wl1, bl1);                         // 13
    k_fb_xr1<<<gn, 256>>>(x, Wr1, br1);                         // 14
    k_edge1<<<NN, 128>>>(ea, We1, att1, bias1);                 // 15

    k_wT_l<<<(HC * HC + 255) / 256, 256>>>(Wl2, HC);            // 16
    k_wT_r<<<(HC * HC + 255) / 256, 256>>>(Wr2, HC);            // 17
    k_mma_xl2<<<gn, 256>>>(bl2);                                // 18
    k_mma_xr2<<<gn, 256>>>(br2);                                // 19
    k_fb_xl2<<<gn, 256>>>(Wl2, bl2);                            // 20
    k_fb_xr2<<<gn, 256>>>(Wr2, br2);                            // 21
    k_edge2<<<NN, 128>>>(ea, We2, att2, bias2, out);            // 22
}

// round 14
// speedup vs baseline: 1.1760x; 1.0320x over previous
#include <cuda_runtime.h>
#include <cuda_bf16.h>
#include <cstdint>

typedef __nv_bfloat16 bf16;

// ---------------- problem constants ----------------
#define NN   16384
#define FF   128
#define RR   16
#define HH   8
#define CC   64
#define HC   512
#define NE   163840
#define NEP  180224          // NE + NN self loops
#define NEG_SLOPE 0.2f
#define SELF_FILL 0.5f

// ---------------- device scratch (only ever touched from device code) ----------------
__device__ int   g_is64;
__device__ int   g_src32[NE];
__device__ int   g_dst32[NE];
__device__ int   g_deg[NN];
__device__ int   g_off[NN + 1];
__device__ int   g_fill[NN];
__device__ int   g_csr_src[NEP];
__device__ int   g_csr_eid[NEP];
__device__ float g_xl1[(size_t)NN * HC];
__device__ float g_xr1[(size_t)NN * HC];
__device__ float g_xl2[(size_t)NN * HC];
__device__ float g_xr2[(size_t)NN * HC];
__device__ __align__(16) bf16 g_xs_hi[(size_t)NN * FF];
__device__ __align__(16) bf16 g_xs_lo[(size_t)NN * FF];
__device__ __align__(16) bf16 g_hs_hi[(size_t)NN * HC];
__device__ __align__(16) bf16 g_hs_lo[(size_t)NN * HC];
__device__ __align__(16) bf16 g_wl_hi[HC * HC];
__device__ __align__(16) bf16 g_wl_lo[HC * HC];
__device__ __align__(16) bf16 g_wr_hi[HC * HC];
__device__ __align__(16) bf16 g_wr_lo[HC * HC];

// ---------------- asm helpers ----------------
#define LDSM_X4(r0, r1, r2, r3, a) \
    asm volatile("ldmatrix.sync.aligned.m8n8.x4.shared.b16 {%0,%1,%2,%3}, [%4];" \
                 : "=r"(r0), "=r"(r1), "=r"(r2), "=r"(r3) : "r"(a))

#define MMA_BF16(d, a0, a1, a2, a3, b0, b1) \
    asm volatile("mma.sync.aligned.m16n8k16.row.col.f32.bf16.bf16.f32 " \
                 "{%0,%1,%2,%3}, {%4,%5,%6,%7}, {%8,%9}, {%0,%1,%2,%3};" \
                 : "+f"((d)[0]), "+f"((d)[1]), "+f"((d)[2]), "+f"((d)[3]) \
                 : "r"(a0), "r"(a1), "r"(a2), "r"(a3), "r"(b0), "r"(b1))

#define CP_ASYNC16(dst, src) \
    asm volatile("cp.async.cg.shared.global [%0], [%1], 16;" :: "r"(dst), "l"(src))
#define CP_COMMIT()  asm volatile("cp.async.commit_group;" ::: "memory")
#define CP_WAIT0()   asm volatile("cp.async.wait_group 0;" ::: "memory")
#define CP_WAIT1()   asm volatile("cp.async.wait_group 1;" ::: "memory")

__device__ __forceinline__ uint32_t smem_to_u32(const void* p) {
    uint32_t a;
    asm("{ .reg .u64 t; cvta.to.shared.u64 t, %1; cvt.u32.u64 %0, t; }" : "=r"(a) : "l"(p));
    return a;
}
__device__ __forceinline__ void fma2(unsigned long long& d, unsigned long long a,
                                     unsigned long long b) {
    asm("fma.rn.f32x2 %0, %1, %2, %0;" : "+l"(d) : "l"(a), "l"(b));
}
__device__ __forceinline__ unsigned long long pack2(float a, float b) {
    unsigned long long r;
    asm("mov.b64 %0, {%1, %2};" : "=l"(r) : "f"(a), "f"(b));
    return r;
}
__device__ __forceinline__ float2 unpack2(unsigned long long v) {
    float2 f;
    asm("mov.b64 {%0, %1}, %2;" : "=f"(f.x), "=f"(f.y) : "l"(v));
    return f;
}
__device__ __forceinline__ uint32_t pkbf(bf16 a, bf16 b) {
    uint16_t ua = *(uint16_t*)&a, ub = *(uint16_t*)&b;
    return (uint32_t)ua | ((uint32_t)ub << 16);
}

// ---------------- dtype detect / convert / CSR ----------------
__global__ void k_detect(const long long* ei) {
    __shared__ int ok;
    if (threadIdx.x == 0) ok = 1;
    __syncthreads();
    for (int i = threadIdx.x; i < 2048; i += blockDim.x) {
        long long v = ei[i];
        if (v < 0 || v >= NN) ok = 0;
    }
    __syncthreads();
    if (threadIdx.x == 0) g_is64 = ok;
}
__global__ void k_init_deg() {
    int n = blockIdx.x * blockDim.x + threadIdx.x;
    if (n < NN) g_deg[n] = 1;
}
__global__ void k_convert(const void* ei) {
    int e = blockIdx.x * blockDim.x + threadIdx.x;
    if (e >= NE) return;
    int s, d;
    if (g_is64) {
        const long long* p = (const long long*)ei;
        s = (int)p[e]; d = (int)p[NE + e];
    } else {
        const int* p = (const int*)ei;
        s = p[e]; d = p[NE + e];
    }
    g_src32[e] = s; g_dst32[e] = d;
    atomicAdd(&g_deg[d], 1);
}
__global__ void k_scan() {
    const int PER = NN / 1024;
    int t = threadIdx.x, lane = t & 31, warp = t >> 5;
    int base = t * PER;
    int loc[PER]; int run = 0;
#pragma unroll
    for (int i = 0; i < PER; i++) { loc[i] = run; run += g_deg[base + i]; }
    int v = run;
#pragma unroll
    for (int o = 1; o < 32; o <<= 1) { int u = __shfl_up_sync(~0u, v, o); if (lane >= o) v += u; }
    __shared__ int ws[32];
    if (lane == 31) ws[warp] = v;
    __syncthreads();
    if (warp == 0) {
        int w = ws[lane];
#pragma unroll
        for (int o = 1; o < 32; o <<= 1) { int u = __shfl_up_sync(~0u, w, o); if (lane >= o) w += u; }
        ws[lane] = w;
    }
    __syncthreads();
    int excl = (warp ? ws[warp - 1] : 0) + (v - run);
#pragma unroll
    for (int i = 0; i < PER; i++) { int o = excl + loc[i]; g_off[base + i] = o; g_fill[base + i] = o; }
    if (t == 1023) g_off[NN] = excl + run;
}
__global__ void k_scatter() {
    int e = blockIdx.x * blockDim.x + threadIdx.x;
    if (e >= NEP) return;
    int s = (e < NE) ? g_src32[e] : (e - NE);
    int d = (e < NE) ? g_dst32[e] : (e - NE);
    int pos = atomicAdd(&g_fill[d], 1);
    g_csr_src[pos] = s; g_csr_eid[pos] = e;
}
__global__ void k_sort() {
    int n = blockIdx.x * blockDim.x + threadIdx.x;
    if (n >= NN) return;
    int b = g_off[n], e = g_off[n + 1];
    for (int i = b + 1; i < e; i++) {
        int ke = g_csr_eid[i], ks = g_csr_src[i];
        int j = i - 1;
        while (j >= b && g_csr_eid[j] > ke) {
            g_csr_eid[j + 1] = g_csr_eid[j]; g_csr_src[j + 1] = g_csr_src[j]; j--;
        }
        g_csr_eid[j + 1] = ke; g_csr_src[j + 1] = ks;
    }
}

// ---------------- split / transpose (globals bound in device code) ----------------
__device__ __forceinline__ void split1(float v, bf16& h, bf16& l) {
    h = __float2bfloat16(v);
    l = __float2bfloat16(v - __bfloat162float(h));
}
__global__ void k_split_x(const float* __restrict__ src) {
    int i = blockIdx.x * blockDim.x + threadIdx.x;
    if (i >= NN * FF) return;
    split1(src[i], g_xs_hi[i], g_xs_lo[i]);
}
__device__ __forceinline__ void wT_body(const float* __restrict__ W, int K,
                                        bf16* __restrict__ hi, bf16* __restrict__ lo) {
    int i = blockIdx.x * blockDim.x + threadIdx.x;
    if (i >= HC * K) return;
    int n = i / K, k = i % K;
    split1(W[(size_t)k * HC + n], hi[i], lo[i]);
}
__global__ void k_wT_l(const float* __restrict__ W, int K) { wT_body(W, K, g_wl_hi, g_wl_lo); }
__global__ void k_wT_r(const float* __restrict__ W, int K) { wT_body(W, K, g_wr_hi, g_wr_lo); }

// ---------------- bf16 HMMA GEMM: cp.async double-buffered, KC=16, pitch 48 ----------------
#define KC       16
#define SPITCH   48
#define TILE_SB  (128 * SPITCH)     // 6144
#define STAGE_B  (4 * TILE_SB)      // 24576
// 2 stages = 49152 bytes static shared

__device__ __forceinline__ void cp_tile(uint32_t smDst, const bf16* __restrict__ g,
                                        size_t row0, int K, int kt, int tid) {
    const char* gb = (const char*)(g + row0 * (size_t)K + (size_t)kt * KC);
    size_t pitchG = (size_t)K * 2;
    int row = tid >> 1, c = (tid & 1) * 16;   // 128 rows x 32B
    CP_ASYNC16(smDst + (uint32_t)(row * SPITCH + c), gb + (size_t)row * pitchG + c);
}

__device__ __forceinline__ void mma_body(const bf16* __restrict__ Ah,
                                         const bf16* __restrict__ Al, int K,
                                         const bf16* __restrict__ Bh,
                                         const bf16* __restrict__ Bl,
                                         const float* __restrict__ bias,
                                         float* __restrict__ C) {
    __shared__ __align__(16) char smem[2 * STAGE_B];
    uint32_t sb = smem_to_u32(smem);
    int tid = threadIdx.x;
    int wid = tid >> 5, lane = tid & 31;
    int wm = wid & 1, wn = wid >> 1;
    size_t rowBase = (size_t)blockIdx.y * 128;
    size_t colBase = (size_t)blockIdx.x * 128;
    int nc = K / KC;

    float acc[4][4][4];
#pragma unroll
    for (int a = 0; a < 4; a++)
#pragma unroll
        for (int b = 0; b < 4; b++)
#pragma unroll
            for (int q = 0; q < 4; q++) acc[a][b][q] = 0.f;

    uint32_t kbyte = (uint32_t)((lane >> 4) * 16);
    uint32_t aOff = (uint32_t)((wm * 64 + (lane & 15)) * SPITCH) + kbyte;
    uint32_t bOff = (uint32_t)((wn * 32 + (lane & 15)) * SPITCH) + kbyte;

    // prologue: stage 0
    {
        uint32_t st = sb;
        cp_tile(st + 0 * TILE_SB, Ah, rowBase, K, 0, tid);
        cp_tile(st + 1 * TILE_SB, Al, rowBase, K, 0, tid);
        cp_tile(st + 2 * TILE_SB, Bh, colBase, K, 0, tid);
        cp_tile(st + 3 * TILE_SB, Bl, colBase, K, 0, tid);
        CP_COMMIT();
    }

    for (int c = 0; c < nc; c++) {
        if (c + 1 < nc) {
            uint32_t st = sb + ((c + 1) & 1) * STAGE_B;
            cp_tile(st + 0 * TILE_SB, Ah, rowBase, K, c + 1, tid);
            cp_tile(st + 1 * TILE_SB, Al, rowBase, K, c + 1, tid);
            cp_tile(st + 2 * TILE_SB, Bh, colBase, K, c + 1, tid);
            cp_tile(st + 3 * TILE_SB, Bl, colBase, K, c + 1, tid);
            CP_COMMIT();
            CP_WAIT1();
        } else {
            CP_WAIT0();
        }
        __syncthreads();

        uint32_t st = sb + (c & 1) * STAGE_B;
        uint32_t ahB = st + 0 * TILE_SB + aOff;
        uint32_t alB = st + 1 * TILE_SB + aOff;
        uint32_t bhB = st + 2 * TILE_SB + bOff;
        uint32_t blB = st + 3 * TILE_SB + bOff;

        uint32_t ah[4][4], al[4][4], bh[2][4], bl[2][4];
#pragma unroll
        for (int mt = 0; mt < 4; mt++) {
            LDSM_X4(ah[mt][0], ah[mt][1], ah[mt][2], ah[mt][3], ahB + mt * 16 * SPITCH);
            LDSM_X4(al[mt][0], al[mt][1], al[mt][2], al[mt][3], alB + mt * 16 * SPITCH);
        }
#pragma unroll
        for (int p = 0; p < 2; p++) {
            LDSM_X4(bh[p][0], bh[p][1], bh[p][2], bh[p][3], bhB + p * 16 * SPITCH);
            LDSM_X4(bl[p][0], bl[p][1], bl[p][2], bl[p][3], blB + p * 16 * SPITCH);
        }
#pragma unroll
        for (int mt = 0; mt < 4; mt++)
#pragma unroll
            for (int nt = 0; nt < 4; nt++) {
                int p = nt >> 1, q = nt & 1;
                MMA_BF16(acc[mt][nt], ah[mt][0], ah[mt][1], ah[mt][2], ah[mt][3],
                         bh[p][q], bh[p][q + 2]);
                MMA_BF16(acc[mt][nt], ah[mt][0], ah[mt][1], ah[mt][2], ah[mt][3],
                         bl[p][q], bl[p][q + 2]);
                MMA_BF16(acc[mt][nt], al[mt][0], al[mt][1], al[mt][2], al[mt][3],
                         bh[p][q], bh[p][q + 2]);
            }
        __syncthreads();
    }

#pragma unroll
    for (int mt = 0; mt < 4; mt++) {
        size_t row = rowBase + wm * 64 + mt * 16 + (lane >> 2);
#pragma unroll
        for (int nt = 0; nt < 4; nt++) {
            size_t col = colBase + wn * 32 + nt * 8 + (lane & 3) * 2;
            float b0 = bias[col], b1 = bias[col + 1];
            *(float2*)(C + row * HC + col) =
                make_float2(acc[mt][nt][0] + b0, acc[mt][nt][1] + b1);
            *(float2*)(C + (row + 8) * HC + col) =
                make_float2(acc[mt][nt][2] + b0, acc[mt][nt][3] + b1);
        }
    }
}

__global__ __launch_bounds__(256, 2) void k_mma_xl1(const float* bias) {
    mma_body(g_xs_hi, g_xs_lo, FF, g_wl_hi, g_wl_lo, bias, g_xl1);
}
__global__ __launch_bounds__(256, 2) void k_mma_xr1(const float* bias) {
    mma_body(g_xs_hi, g_xs_lo, FF, g_wr_hi, g_wr_lo, bias, g_xr1);
}
__global__ __launch_bounds__(256, 2) void k_mma_xl2(const float* bias) {
    mma_body(g_hs_hi, g_hs_lo, HC, g_wl_hi, g_wl_lo, bias, g_xl2);
}
__global__ __launch_bounds__(256, 2) void k_mma_xr2(const float* bias) {
    mma_body(g_hs_hi, g_hs_lo, HC, g_wr_hi, g_wr_lo, bias, g_xr2);
}

// ---------------- GATv2 edge pass with FUSED edge-feature transform ----------------
__device__ __forceinline__ void gat_edge_fused(const float* __restrict__ xl,
                                               const float* __restrict__ xr,
                                               const float* __restrict__ ea,
                                               const float* __restrict__ We,
                                               const float* __restrict__ att,
                                               const float* __restrict__ bias,
                                               float* __restrict__ out,
                                               bool concat) {
    __shared__ float sOut[HC];
    int tid = threadIdx.x;
    int n = blockIdx.x;

    // preload this thread's 4 columns of We (RR x 4 floats) as packed pairs
    unsigned long long we2[RR][2];
    unsigned long long self0 = 0ull, self1 = 0ull;
    const unsigned long long half2 = pack2(SELF_FILL, SELF_FILL);
#pragma unroll
    for (int k = 0; k < RR; k++) {
        float4 w = *(const float4*)&We[k * HC + tid * 4];
        we2[k][0] = pack2(w.x, w.y);
        we2[k][1] = pack2(w.z, w.w);
        fma2(self0, half2, we2[k][0]);     // self-loop ep (constant per column)
        fma2(self1, half2, we2[k][1]);
    }

    float4 attv = ((const float4*)att)[tid];
    float4 xr4 = ((const float4*)(xr + (size_t)n * HC))[tid];

    float m = -1e30f, s = 0.f;
    float ax = 0.f, ay = 0.f, az = 0.f, aw = 0.f;
    int b = g_off[n], e = g_off[n + 1];
    for (int i = b; i < e; i++) {
        int src = g_csr_src[i];
        int eid = g_csr_eid[i];
        float4 xl4 = ((const float4*)(xl + (size_t)src * HC))[tid];
        float2 pa, pb;
        if (eid < NE) {
            const float4* er = (const float4*)(ea + (size_t)eid * RR);
            float4 e0 = er[0], e1 = er[1], e2 = er[2], e3 = er[3];
            float ev[RR] = {e0.x, e0.y, e0.z, e0.w, e1.x, e1.y, e1.z, e1.w,
                            e2.x, e2.y, e2.z, e2.w, e3.x, e3.y, e3.z, e3.w};
            unsigned long long p0 = 0ull, p1 = 0ull;
#pragma unroll
            for (int k = 0; k < RR; k++) {
                unsigned long long ee = pack2(ev[k], ev[k]);
                fma2(p0, ee, we2[k][0]);
                fma2(p1, ee, we2[k][1]);
            }
            pa = unpack2(p0); pb = unpack2(p1);
        } else {
            pa = unpack2(self0); pb = unpack2(self1);
        }
        float zx = xl4.x + xr4.x + pa.x; zx = zx > 0.f ? zx : NEG_SLOPE * zx;
        float zy = xl4.y + xr4.y + pa.y; zy = zy > 0.f ? zy : NEG_SLOPE * zy;
        float zz = xl4.z + xr4.z + pb.x; zz = zz > 0.f ? zz : NEG_SLOPE * zz;
        float zw = xl4.w + xr4.w + pb.y; zw = zw > 0.f ? zw : NEG_SLOPE * zw;
        float p = zx * attv.x + zy * attv.y + zz * attv.z + zw * attv.w;
        p += __shfl_xor_sync(~0u, p, 8);
        p += __shfl_xor_sync(~0u, p, 4);
        p += __shfl_xor_sync(~0u, p, 2);
        p += __shfl_xor_sync(~0u, p, 1);
        float mN = fmaxf(m, p);
        float sc = __expf(m - mN);
        float w  = __expf(p - mN);
        s  = s  * sc + w;
        ax = ax * sc + w * xl4.x;
        ay = ay * sc + w * xl4.y;
        az = az * sc + w * xl4.z;
        aw = aw * sc + w * xl4.w;
        m = mN;
    }
    float inv = 1.f / (s + 1e-16f);
    if (concat) {
        float4 o = make_float4(ax * inv + bias[tid * 4 + 0], ay * inv + bias[tid * 4 + 1],
                               az * inv + bias[tid * 4 + 2], aw * inv + bias[tid * 4 + 3]);
        size_t base = (size_t)n * HC + tid * 4;
        // bf16 split is the ONLY layer-2 GEMM input (no fp32 h1 buffer needed)
        bf16 h0, l0, h1, l1, h2, l2, h3, l3;
        split1(o.x, h0, l0); split1(o.y, h1, l1);
        split1(o.z, h2, l2); split1(o.w, h3, l3);
        *(uint2*)&g_hs_hi[base] = make_uint2(pkbf(h0, h1), pkbf(h2, h3));
        *(uint2*)&g_hs_lo[base] = make_uint2(pkbf(l0, l1), pkbf(l2, l3));
    } else {
        sOut[tid * 4 + 0] = ax * inv; sOut[tid * 4 + 1] = ay * inv;
        sOut[tid * 4 + 2] = az * inv; sOut[tid * 4 + 3] = aw * inv;
        __syncthreads();
        if (tid < CC) {
            float acc = 0.f;
#pragma unroll
            for (int h = 0; h < HH; h++) acc += sOut[h * CC + tid];
            out[(size_t)n * CC + tid] = acc * (1.f / HH) + bias[tid];
        }
    }
}
__global__ __launch_bounds__(128) void k_edge1(const float* ea, const float* We,
                                               const float* att, const float* bias) {
    gat_edge_fused(g_xl1, g_xr1, ea, We, att, bias, nullptr, true);
}
__global__ __launch_bounds__(128) void k_edge2(const float* ea, const float* We,
                                               const float* att, const float* bias,
                                               float* out) {
    gat_edge_fused(g_xl2, g_xr2, ea, We, att, bias, out, false);
}

// ---------------- launch ----------------
extern "C" void kernel_launch(void* const* d_in, const int* in_sizes, int n_in,
                              void* d_out, int out_size) {
    const float* x     = (const float*)d_in[0];
    const void*  ei    = d_in[1];
    const float* ea    = (const float*)d_in[2];
    const float* Wl1   = (const float*)d_in[3];
    const float* bl1   = (const float*)d_in[4];
    const float* Wr1   = (const float*)d_in[5];
    const float* br1   = (const float*)d_in[6];
    const float* We1   = (const float*)d_in[7];
    const float* att1  = (const float*)d_in[8];
    const float* bias1 = (const float*)d_in[9];
    const float* Wl2   = (const float*)d_in[10];
    const float* bl2   = (const float*)d_in[11];
    const float* Wr2   = (const float*)d_in[12];
    const float* br2   = (const float*)d_in[13];
    const float* We2   = (const float*)d_in[14];
    const float* att2  = (const float*)d_in[15];
    const float* bias2 = (const float*)d_in[16];
    float* out = (float*)d_out;

    dim3 gn(HC / 128, NN / 128);

    // launch #4 is the HMMA GEMM (ncu -s 5 -c 1 slot)
    k_detect<<<1, 256>>>((const long long*)ei);                 // 1
    k_split_x<<<(NN * FF + 255) / 256, 256>>>(x);               // 2
    k_wT_l<<<(HC * FF + 255) / 256, 256>>>(Wl1, FF);            // 3
    k_mma_xl1<<<gn, 256>>>(bl1);                                // 4  <- profile me
    k_init_deg<<<NN / 256, 256>>>();                            // 5
    k_convert<<<NE / 256, 256>>>(ei);                           // 6
    k_scan<<<1, 1024>>>();                                      // 7
    k_scatter<<<(NEP + 255) / 256, 256>>>();                    // 8
    k_sort<<<(NN + 127) / 128, 128>>>();                        // 9
    k_wT_r<<<(HC * FF + 255) / 256, 256>>>(Wr1, FF);            // 10
    k_mma_xr1<<<gn, 256>>>(br1);                                // 11
    k_edge1<<<NN, 128>>>(ea, We1, att1, bias1);                 // 12

    k_wT_l<<<(HC * HC + 255) / 256, 256>>>(Wl2, HC);            // 13
    k_wT_r<<<(HC * HC + 255) / 256, 256>>>(Wr2, HC);            // 14
    k_mma_xl2<<<gn, 256>>>(bl2);                                // 15
    k_mma_xr2<<<gn, 256>>>(br2);                                // 16
    k_edge2<<<NN, 128>>>(ea, We2, att2, bias2, out);            // 17
}

// round 15
// speedup vs baseline: 1.2448x; 1.0585x over previous
#include <cuda_runtime.h>
#include <cuda_bf16.h>
#include <cstdint>

typedef __nv_bfloat16 bf16;

// ---------------- problem constants ----------------
#define NN   16384
#define FF   128
#define RR   16
#define HH   8
#define CC   64
#define HC   512
#define NE   163840
#define NEP  180224          // NE + NN self loops
#define NEG_SLOPE 0.2f
#define SELF_FILL 0.5f

// ---------------- device scratch (only ever touched from device code) ----------------
__device__ int   g_is64;
__device__ int   g_src32[NE];
__device__ int   g_dst32[NE];
__device__ int   g_deg[NN];
__device__ int   g_off[NN + 1];
__device__ int   g_fill[NN];
__device__ int   g_csr_src[NEP];
__device__ int   g_csr_eid[NEP];
__device__ float g_xl1[(size_t)NN * HC];
__device__ float g_xr1[(size_t)NN * HC];
__device__ float g_xl2[(size_t)NN * HC];
__device__ float g_xr2[(size_t)NN * HC];
__device__ __align__(16) bf16 g_xs_hi[(size_t)NN * FF];
__device__ __align__(16) bf16 g_xs_lo[(size_t)NN * FF];
__device__ __align__(16) bf16 g_hs_hi[(size_t)NN * HC];
__device__ __align__(16) bf16 g_hs_lo[(size_t)NN * HC];
__device__ __align__(16) bf16 g_wl_hi[HC * HC];
__device__ __align__(16) bf16 g_wl_lo[HC * HC];
__device__ __align__(16) bf16 g_wr_hi[HC * HC];
__device__ __align__(16) bf16 g_wr_lo[HC * HC];

// ---------------- asm helpers ----------------
#define LDSM_X4(r0, r1, r2, r3, a) \
    asm volatile("ldmatrix.sync.aligned.m8n8.x4.shared.b16 {%0,%1,%2,%3}, [%4];" \
                 : "=r"(r0), "=r"(r1), "=r"(r2), "=r"(r3) : "r"(a))

#define MMA_BF16(d, a0, a1, a2, a3, b0, b1) \
    asm volatile("mma.sync.aligned.m16n8k16.row.col.f32.bf16.bf16.f32 " \
                 "{%0,%1,%2,%3}, {%4,%5,%6,%7}, {%8,%9}, {%0,%1,%2,%3};" \
                 : "+f"((d)[0]), "+f"((d)[1]), "+f"((d)[2]), "+f"((d)[3]) \
                 : "r"(a0), "r"(a1), "r"(a2), "r"(a3), "r"(b0), "r"(b1))

#define CP_ASYNC16(dst, src) \
    asm volatile("cp.async.cg.shared.global [%0], [%1], 16;" :: "r"(dst), "l"(src))
#define CP_COMMIT()  asm volatile("cp.async.commit_group;" ::: "memory")
#define CP_WAIT0()   asm volatile("cp.async.wait_group 0;" ::: "memory")
#define CP_WAIT1()   asm volatile("cp.async.wait_group 1;" ::: "memory")

__device__ __forceinline__ uint32_t smem_to_u32(const void* p) {
    uint32_t a;
    asm("{ .reg .u64 t; cvta.to.shared.u64 t, %1; cvt.u32.u64 %0, t; }" : "=r"(a) : "l"(p));
    return a;
}
__device__ __forceinline__ void fma2(unsigned long long& d, unsigned long long a,
                                     unsigned long long b) {
    asm("fma.rn.f32x2 %0, %1, %2, %0;" : "+l"(d) : "l"(a), "l"(b));
}
__device__ __forceinline__ unsigned long long pack2(float a, float b) {
    unsigned long long r;
    asm("mov.b64 %0, {%1, %2};" : "=l"(r) : "f"(a), "f"(b));
    return r;
}
__device__ __forceinline__ float2 unpack2(unsigned long long v) {
    float2 f;
    asm("mov.b64 {%0, %1}, %2;" : "=f"(f.x), "=f"(f.y) : "l"(v));
    return f;
}
__device__ __forceinline__ uint32_t pkbf(bf16 a, bf16 b) {
    uint16_t ua = *(uint16_t*)&a, ub = *(uint16_t*)&b;
    return (uint32_t)ua | ((uint32_t)ub << 16);
}

// ---------------- dtype detect / convert / CSR ----------------
__global__ void k_detect(const long long* ei) {
    __shared__ int ok;
    if (threadIdx.x == 0) ok = 1;
    __syncthreads();
    for (int i = threadIdx.x; i < 2048; i += blockDim.x) {
        long long v = ei[i];
        if (v < 0 || v >= NN) ok = 0;
    }
    __syncthreads();
    if (threadIdx.x == 0) g_is64 = ok;
}
__global__ void k_init_deg() {
    int n = blockIdx.x * blockDim.x + threadIdx.x;
    if (n < NN) g_deg[n] = 1;
}
__global__ void k_convert(const void* ei) {
    int e = blockIdx.x * blockDim.x + threadIdx.x;
    if (e >= NE) return;
    int s, d;
    if (g_is64) {
        const long long* p = (const long long*)ei;
        s = (int)p[e]; d = (int)p[NE + e];
    } else {
        const int* p = (const int*)ei;
        s = p[e]; d = p[NE + e];
    }
    g_src32[e] = s; g_dst32[e] = d;
    atomicAdd(&g_deg[d], 1);
}
__global__ void k_scan() {
    const int PER = NN / 1024;
    int t = threadIdx.x, lane = t & 31, warp = t >> 5;
    int base = t * PER;
    int loc[PER]; int run = 0;
#pragma unroll
    for (int i = 0; i < PER; i++) { loc[i] = run; run += g_deg[base + i]; }
    int v = run;
#pragma unroll
    for (int o = 1; o < 32; o <<= 1) { int u = __shfl_up_sync(~0u, v, o); if (lane >= o) v += u; }
    __shared__ int ws[32];
    if (lane == 31) ws[warp] = v;
    __syncthreads();
    if (warp == 0) {
        int w = ws[lane];
#pragma unroll
        for (int o = 1; o < 32; o <<= 1) { int u = __shfl_up_sync(~0u, w, o); if (lane >= o) w += u; }
        ws[lane] = w;
    }
    __syncthreads();
    int excl = (warp ? ws[warp - 1] : 0) + (v - run);
#pragma unroll
    for (int i = 0; i < PER; i++) { int o = excl + loc[i]; g_off[base + i] = o; g_fill[base + i] = o; }
    if (t == 1023) g_off[NN] = excl + run;
}
__global__ void k_scatter() {
    int e = blockIdx.x * blockDim.x + threadIdx.x;
    if (e >= NEP) return;
    int s = (e < NE) ? g_src32[e] : (e - NE);
    int d = (e < NE) ? g_dst32[e] : (e - NE);
    int pos = atomicAdd(&g_fill[d], 1);
    g_csr_src[pos] = s; g_csr_eid[pos] = e;
}
__global__ void k_sort() {
    int n = blockIdx.x * blockDim.x + threadIdx.x;
    if (n >= NN) return;
    int b = g_off[n], e = g_off[n + 1];
    for (int i = b + 1; i < e; i++) {
        int ke = g_csr_eid[i], ks = g_csr_src[i];
        int j = i - 1;
        while (j >= b && g_csr_eid[j] > ke) {
            g_csr_eid[j + 1] = g_csr_eid[j]; g_csr_src[j + 1] = g_csr_src[j]; j--;
        }
        g_csr_eid[j + 1] = ke; g_csr_src[j + 1] = ks;
    }
}

// ---------------- split / transpose (globals bound in device code) ----------------
__device__ __forceinline__ void split1(float v, bf16& h, bf16& l) {
    h = __float2bfloat16(v);
    l = __float2bfloat16(v - __bfloat162float(h));
}
__global__ void k_split_x(const float* __restrict__ src) {
    int i = blockIdx.x * blockDim.x + threadIdx.x;
    if (i >= NN * FF) return;
    split1(src[i], g_xs_hi[i], g_xs_lo[i]);
}
// both weight transposes in one launch: blockIdx.y = 0 -> Wl, 1 -> Wr
__global__ void k_wT2(const float* __restrict__ Wl, const float* __restrict__ Wr, int K) {
    int i = blockIdx.x * blockDim.x + threadIdx.x;
    if (i >= HC * K) return;
    int n = i / K, k = i % K;
    if (blockIdx.y == 0) {
        split1(Wl[(size_t)k * HC + n], g_wl_hi[i], g_wl_lo[i]);
    } else {
        split1(Wr[(size_t)k * HC + n], g_wr_hi[i], g_wr_lo[i]);
    }
}

// ---------------- bf16 HMMA GEMM: cp.async double-buffered, KC=16, pitch 48 ----------------
#define KC       16
#define SPITCH   48
#define TILE_SB  (128 * SPITCH)     // 6144
#define STAGE_B  (4 * TILE_SB)      // 24576
// 2 stages = 49152 bytes static shared

__device__ __forceinline__ void cp_tile(uint32_t smDst, const bf16* __restrict__ g,
                                        size_t row0, int K, int kt, int tid) {
    const char* gb = (const char*)(g + row0 * (size_t)K + (size_t)kt * KC);
    size_t pitchG = (size_t)K * 2;
    int row = tid >> 1, c = (tid & 1) * 16;   // 128 rows x 32B
    CP_ASYNC16(smDst + (uint32_t)(row * SPITCH + c), gb + (size_t)row * pitchG + c);
}

__device__ __forceinline__ void mma_body(const bf16* __restrict__ Ah,
                                         const bf16* __restrict__ Al, int K,
                                         const bf16* __restrict__ Bh,
                                         const bf16* __restrict__ Bl,
                                         const float* __restrict__ bias,
                                         float* __restrict__ C) {
    __shared__ __align__(16) char smem[2 * STAGE_B];
    uint32_t sb = smem_to_u32(smem);
    int tid = threadIdx.x;
    int wid = tid >> 5, lane = tid & 31;
    int wm = wid & 1, wn = wid >> 1;
    size_t rowBase = (size_t)blockIdx.y * 128;
    size_t colBase = (size_t)blockIdx.x * 128;
    int nc = K / KC;

    float acc[4][4][4];
#pragma unroll
    for (int a = 0; a < 4; a++)
#pragma unroll
        for (int b = 0; b < 4; b++)
#pragma unroll
            for (int q = 0; q < 4; q++) acc[a][b][q] = 0.f;

    uint32_t kbyte = (uint32_t)((lane >> 4) * 16);
    uint32_t aOff = (uint32_t)((wm * 64 + (lane & 15)) * SPITCH) + kbyte;
    uint32_t bOff = (uint32_t)((wn * 32 + (lane & 15)) * SPITCH) + kbyte;

    // prologue: stage 0
    {
        uint32_t st = sb;
        cp_tile(st + 0 * TILE_SB, Ah, rowBase, K, 0, tid);
        cp_tile(st + 1 * TILE_SB, Al, rowBase, K, 0, tid);
        cp_tile(st + 2 * TILE_SB, Bh, colBase, K, 0, tid);
        cp_tile(st + 3 * TILE_SB, Bl, colBase, K, 0, tid);
        CP_COMMIT();
    }

    for (int c = 0; c < nc; c++) {
        if (c + 1 < nc) {
            uint32_t st = sb + ((c + 1) & 1) * STAGE_B;
            cp_tile(st + 0 * TILE_SB, Ah, rowBase, K, c + 1, tid);
            cp_tile(st + 1 * TILE_SB, Al, rowBase, K, c + 1, tid);
            cp_tile(st + 2 * TILE_SB, Bh, colBase, K, c + 1, tid);
            cp_tile(st + 3 * TILE_SB, Bl, colBase, K, c + 1, tid);
            CP_COMMIT();
            CP_WAIT1();
        } else {
            CP_WAIT0();
        }
        __syncthreads();

        uint32_t st = sb + (c & 1) * STAGE_B;
        uint32_t ahB = st + 0 * TILE_SB + aOff;
        uint32_t alB = st + 1 * TILE_SB + aOff;
        uint32_t bhB = st + 2 * TILE_SB + bOff;
        uint32_t blB = st + 3 * TILE_SB + bOff;

        uint32_t ah[4][4], al[4][4], bh[2][4], bl[2][4];
#pragma unroll
        for (int mt = 0; mt < 4; mt++) {
            LDSM_X4(ah[mt][0], ah[mt][1], ah[mt][2], ah[mt][3], ahB + mt * 16 * SPITCH);
            LDSM_X4(al[mt][0], al[mt][1], al[mt][2], al[mt][3], alB + mt * 16 * SPITCH);
        }
#pragma unroll
        for (int p = 0; p < 2; p++) {
            LDSM_X4(bh[p][0], bh[p][1], bh[p][2], bh[p][3], bhB + p * 16 * SPITCH);
            LDSM_X4(bl[p][0], bl[p][1], bl[p][2], bl[p][3], blB + p * 16 * SPITCH);
        }
#pragma unroll
        for (int mt = 0; mt < 4; mt++)
#pragma unroll
            for (int nt = 0; nt < 4; nt++) {
                int p = nt >> 1, q = nt & 1;
                MMA_BF16(acc[mt][nt], ah[mt][0], ah[mt][1], ah[mt][2], ah[mt][3],
                         bh[p][q], bh[p][q + 2]);
                MMA_BF16(acc[mt][nt], ah[mt][0], ah[mt][1], ah[mt][2], ah[mt][3],
                         bl[p][q], bl[p][q + 2]);
                MMA_BF16(acc[mt][nt], al[mt][0], al[mt][1], al[mt][2], al[mt][3],
                         bh[p][q], bh[p][q + 2]);
            }
        __syncthreads();
    }

#pragma unroll
    for (int mt = 0; mt < 4; mt++) {
        size_t row = rowBase + wm * 64 + mt * 16 + (lane >> 2);
#pragma unroll
        for (int nt = 0; nt < 4; nt++) {
            size_t col = colBase + wn * 32 + nt * 8 + (lane & 3) * 2;
            float b0 = bias[col], b1 = bias[col + 1];
            *(float2*)(C + row * HC + col) =
                make_float2(acc[mt][nt][0] + b0, acc[mt][nt][1] + b1);
            *(float2*)(C + (row + 8) * HC + col) =
                make_float2(acc[mt][nt][2] + b0, acc[mt][nt][3] + b1);
        }
    }
}

// merged xl/xr GEMM pairs: blockIdx.z = 0 -> Wl path, 1 -> Wr path
__global__ __launch_bounds__(256, 2) void k_mma_x1(const float* bl, const float* br) {
    if (blockIdx.z == 0)
        mma_body(g_xs_hi, g_xs_lo, FF, g_wl_hi, g_wl_lo, bl, g_xl1);
    else
        mma_body(g_xs_hi, g_xs_lo, FF, g_wr_hi, g_wr_lo, br, g_xr1);
}
__global__ __launch_bounds__(256, 2) void k_mma_x2(const float* bl, const float* br) {
    if (blockIdx.z == 0)
        mma_body(g_hs_hi, g_hs_lo, HC, g_wl_hi, g_wl_lo, bl, g_xl2);
    else
        mma_body(g_hs_hi, g_hs_lo, HC, g_wr_hi, g_wr_lo, br, g_xr2);
}

// ---------------- GATv2 edge pass with FUSED edge-feature transform ----------------
__device__ __forceinline__ void gat_edge_fused(const float* __restrict__ xl,
                                               const float* __restrict__ xr,
                                               const float* __restrict__ ea,
                                               const float* __restrict__ We,
                                               const float* __restrict__ att,
                                               const float* __restrict__ bias,
                                               float* __restrict__ out,
                                               bool concat) {
    __shared__ float sOut[HC];
    int tid = threadIdx.x;
    int n = blockIdx.x;

    // preload this thread's 4 columns of We (RR x 4 floats) as packed pairs
    unsigned long long we2[RR][2];
    unsigned long long self0 = 0ull, self1 = 0ull;
    const unsigned long long half2 = pack2(SELF_FILL, SELF_FILL);
#pragma unroll
    for (int k = 0; k < RR; k++) {
        float4 w = *(const float4*)&We[k * HC + tid * 4];
        we2[k][0] = pack2(w.x, w.y);
        we2[k][1] = pack2(w.z, w.w);
        fma2(self0, half2, we2[k][0]);     // self-loop ep (constant per column)
        fma2(self1, half2, we2[k][1]);
    }

    float4 attv = ((const float4*)att)[tid];
    float4 xr4 = ((const float4*)(xr + (size_t)n * HC))[tid];

    float m = -1e30f, s = 0.f;
    float ax = 0.f, ay = 0.f, az = 0.f, aw = 0.f;
    int b = g_off[n], e = g_off[n + 1];
    for (int i = b; i < e; i++) {
        int src = g_csr_src[i];
        int eid = g_csr_eid[i];
        float4 xl4 = ((const float4*)(xl + (size_t)src * HC))[tid];
        float2 pa, pb;
        if (eid < NE) {
            const float4* er = (const float4*)(ea + (size_t)eid * RR);
            float4 e0 = er[0], e1 = er[1], e2 = er[2], e3 = er[3];
            float ev[RR] = {e0.x, e0.y, e0.z, e0.w, e1.x, e1.y, e1.z, e1.w,
                            e2.x, e2.y, e2.z, e2.w, e3.x, e3.y, e3.z, e3.w};
            unsigned long long p0 = 0ull, p1 = 0ull;
#pragma unroll
            for (int k = 0; k < RR; k++) {
                unsigned long long ee = pack2(ev[k], ev[k]);
                fma2(p0, ee, we2[k][0]);
                fma2(p1, ee, we2[k][1]);
            }
            pa = unpack2(p0); pb = unpack2(p1);
        } else {
            pa = unpack2(self0); pb = unpack2(self1);
        }
        float zx = xl4.x + xr4.x + pa.x; zx = zx > 0.f ? zx : NEG_SLOPE * zx;
        float zy = xl4.y + xr4.y + pa.y; zy = zy > 0.f ? zy : NEG_SLOPE * zy;
        float zz = xl4.z + xr4.z + pb.x; zz = zz > 0.f ? zz : NEG_SLOPE * zz;
        float zw = xl4.w + xr4.w + pb.y; zw = zw > 0.f ? zw : NEG_SLOPE * zw;
        float p = zx * attv.x + zy * attv.y + zz * attv.z + zw * attv.w;
        p += __shfl_xor_sync(~0u, p, 8);
        p += __shfl_xor_sync(~0u, p, 4);
        p += __shfl_xor_sync(~0u, p, 2);
        p += __shfl_xor_sync(~0u, p, 1);
        float mN = fmaxf(m, p);
        float sc = __expf(m - mN);
        float w  = __expf(p - mN);
        s  = s  * sc + w;
        ax = ax * sc + w * xl4.x;
        ay = ay * sc + w * xl4.y;
        az = az * sc + w * xl4.z;
        aw = aw * sc + w * xl4.w;
        m = mN;
    }
    float inv = 1.f / (s + 1e-16f);
    if (concat) {
        float4 o = make_float4(ax * inv + bias[tid * 4 + 0], ay * inv + bias[tid * 4 + 1],
                               az * inv + bias[tid * 4 + 2], aw * inv + bias[tid * 4 + 3]);
        size_t base = (size_t)n * HC + tid * 4;
        // bf16 split is the ONLY layer-2 GEMM input
        bf16 h0, l0, h1, l1, h2, l2, h3, l3;
        split1(o.x, h0, l0); split1(o.y, h1, l1);
        split1(o.z, h2, l2); split1(o.w, h3, l3);
        *(uint2*)&g_hs_hi[base] = make_uint2(pkbf(h0, h1), pkbf(h2, h3));
        *(uint2*)&g_hs_lo[base] = make_uint2(pkbf(l0, l1), pkbf(l2, l3));
    } else {
        sOut[tid * 4 + 0] = ax * inv; sOut[tid * 4 + 1] = ay * inv;
        sOut[tid * 4 + 2] = az * inv; sOut[tid * 4 + 3] = aw * inv;
        __syncthreads();
        if (tid < CC) {
            float acc = 0.f;
#pragma unroll
            for (int h = 0; h < HH; h++) acc += sOut[h * CC + tid];
            out[(size_t)n * CC + tid] = acc * (1.f / HH) + bias[tid];
        }
    }
}
__global__ __launch_bounds__(128) void k_edge1(const float* ea, const float* We,
                                               const float* att, const float* bias) {
    gat_edge_fused(g_xl1, g_xr1, ea, We, att, bias, nullptr, true);
}
__global__ __launch_bounds__(128) void k_edge2(const float* ea, const float* We,
                                               const float* att, const float* bias,
                                               float* out) {
    gat_edge_fused(g_xl2, g_xr2, ea, We, att, bias, out, false);
}

// ---------------- launch ----------------
extern "C" void kernel_launch(void* const* d_in, const int* in_sizes, int n_in,
                              void* d_out, int out_size) {
    const float* x     = (const float*)d_in[0];
    const void*  ei    = d_in[1];
    const float* ea    = (const float*)d_in[2];
    const float* Wl1   = (const float*)d_in[3];
    const float* bl1   = (const float*)d_in[4];
    const float* Wr1   = (const float*)d_in[5];
    const float* br1   = (const float*)d_in[6];
    const float* We1   = (const float*)d_in[7];
    const float* att1  = (const float*)d_in[8];
    const float* bias1 = (const float*)d_in[9];
    const float* Wl2   = (const float*)d_in[10];
    const float* bl2   = (const float*)d_in[11];
    const float* Wr2   = (const float*)d_in[12];
    const float* br2   = (const float*)d_in[13];
    const float* We2   = (const float*)d_in[14];
    const float* att2  = (const float*)d_in[15];
    const float* bias2 = (const float*)d_in[16];
    float* out = (float*)d_out;

    dim3 gn(HC / 128, NN / 128, 2);      // merged xl/xr pair (z selects path)
    dim3 wt1((HC * FF + 255) / 256, 2);  // merged weight transpose pair
    dim3 wt2((HC * HC + 255) / 256, 2);

    // launch #4 is the merged layer-1 HMMA GEMM pair (ncu -s 5 -c 1 slot)
    k_detect<<<1, 256>>>((const long long*)ei);                 // 1
    k_split_x<<<(NN * FF + 255) / 256, 256>>>(x);               // 2
    k_wT2<<<wt1, 256>>>(Wl1, Wr1, FF);                          // 3
    k_mma_x1<<<gn, 256>>>(bl1, br1);                            // 4  <- profile me
    k_init_deg<<<NN / 256, 256>>>();                            // 5
    k_convert<<<NE / 256, 256>>>(ei);                           // 6
    k_scan<<<1, 1024>>>();                                      // 7
    k_scatter<<<(NEP + 255) / 256, 256>>>();                    // 8
    k_sort<<<(NN + 127) / 128, 128>>>();                        // 9
    k_edge1<<<NN, 128>>>(ea, We1, att1, bias1);                 // 10

    k_wT2<<<wt2, 256>>>(Wl2, Wr2, HC);                          // 11
    k_mma_x2<<<gn, 256>>>(bl2, br2);                            // 12
    k_edge2<<<NN, 128>>>(ea, We2, att2, bias2, out);            // 13
}